// round 2
// baseline (speedup 1.0000x reference)
#include <cuda_runtime.h>

#define N_NODES 50000
#define N_EDGES 500000
#define D_NODE  64
#define D_EDGE  32
#define MSG     160
#define HID     224
#define ALPHA   0.01f

// 32 MB scratch for segment-sum accumulation (allocation-free rule: __device__ global)
__device__ float g_msum[(size_t)N_NODES * MSG];

__device__ __forceinline__ float lrelu(float v) { return v > 0.f ? v : ALPHA * v; }

// ---------------------------------------------------------------------------
// Kernel 0: zero the accumulator
// ---------------------------------------------------------------------------
__global__ void zero_msum_kernel() {
    size_t n4 = (size_t)N_NODES * MSG / 4;
    float4* p = (float4*)g_msum;
    for (size_t i = (size_t)blockIdx.x * blockDim.x + threadIdx.x; i < n4;
         i += (size_t)gridDim.x * blockDim.x)
        p[i] = make_float4(0.f, 0.f, 0.f, 0.f);
}

// ---------------------------------------------------------------------------
// Kernel 1: per-edge message GEMM + LeakyReLU + atomic scatter to g_msum
//   Tile: 64 edges x 160 outputs, full W_msg (160x160) in smem.
//   Thread layout: 256 threads = 16(tx: 10 outputs) x 16(ty: 4 edges)
// ---------------------------------------------------------------------------
#define BE    64
#define WSTR  161   // W smem row stride (conflict-free: 10*tx*161 % 32 = 10*tx % 32)
#define XSTR  164   // X smem row stride (16B aligned, (4e+k)%32 distinct)

#define EDGE_SMEM_BYTES (((MSG*WSTR) + (BE*XSTR) + MSG) * 4 + BE * 4)

__global__ __launch_bounds__(256, 1) void edge_kernel(
    const float* __restrict__ h_n, const float* __restrict__ h_e,
    const int* __restrict__ src, const int* __restrict__ dst,
    const float* __restrict__ Wm, const float* __restrict__ bm)
{
    extern __shared__ float smem[];
    float* Wsm = smem;                    // MSG * WSTR
    float* Xsm = Wsm + MSG * WSTR;        // BE * XSTR
    float* bsm = Xsm + BE * XSTR;         // MSG
    int*   dsm = (int*)(bsm + MSG);       // BE

    const int tid = threadIdx.x;
    const int e0  = blockIdx.x * BE;

    // Load full W_msg into smem (row-major, padded stride)
    for (int i = tid; i < MSG * 40; i += 256) {
        int r = i / 40, c = (i % 40) * 4;
        float4 v = *(const float4*)(Wm + r * MSG + c);
        float* dp = Wsm + r * WSTR + c;
        dp[0] = v.x; dp[1] = v.y; dp[2] = v.z; dp[3] = v.w;
    }
    if (tid < MSG) bsm[tid] = bm[tid];
    if (tid < BE) {
        int e = e0 + tid;
        dsm[tid] = (e < N_EDGES) ? dst[e] : -1;
    }
    // Gather X tile: per edge 40 float4 = [h_n[src](16) | h_n[dst](16) | h_e(8)]
    for (int i = tid; i < BE * 40; i += 256) {
        int le = i / 40, j = i % 40;
        int e = e0 + le;
        float4 v = make_float4(0.f, 0.f, 0.f, 0.f);
        if (e < N_EDGES) {
            if (j < 16)      v = ((const float4*)(h_n + (size_t)src[e] * D_NODE))[j];
            else if (j < 32) v = ((const float4*)(h_n + (size_t)dst[e] * D_NODE))[j - 16];
            else             v = ((const float4*)(h_e + (size_t)e * D_EDGE))[j - 32];
        }
        *(float4*)(Xsm + le * XSTR + j * 4) = v;
    }
    __syncthreads();

    const int tx = tid & 15;     // output group: n0 = tx*10
    const int ty = tid >> 4;     // edge group: 4 edges
    const int n0 = tx * 10;
    const float* xb = Xsm + (ty * 4) * XSTR;

    float acc[4][10];
    #pragma unroll
    for (int m = 0; m < 4; m++)
        #pragma unroll
        for (int j = 0; j < 10; j++) acc[m][j] = bsm[n0 + j];

    #pragma unroll 2
    for (int k = 0; k < MSG; k++) {
        float w[10];
        #pragma unroll
        for (int j = 0; j < 10; j++) w[j] = Wsm[(n0 + j) * WSTR + k];
        float x0 = xb[k];
        float x1 = xb[XSTR + k];
        float x2 = xb[2 * XSTR + k];
        float x3 = xb[3 * XSTR + k];
        #pragma unroll
        for (int j = 0; j < 10; j++) {
            acc[0][j] = fmaf(x0, w[j], acc[0][j]);
            acc[1][j] = fmaf(x1, w[j], acc[1][j]);
            acc[2][j] = fmaf(x2, w[j], acc[2][j]);
            acc[3][j] = fmaf(x3, w[j], acc[3][j]);
        }
    }

    // LeakyReLU + vectorized atomic scatter (red.v2.f32, 8B aligned: n0 even)
    #pragma unroll
    for (int m = 0; m < 4; m++) {
        int d = dsm[ty * 4 + m];
        if (d < 0) continue;
        float* base = g_msum + (size_t)d * MSG + n0;
        #pragma unroll
        for (int j = 0; j < 10; j += 2) {
            float a = lrelu(acc[m][j]);
            float c = lrelu(acc[m][j + 1]);
            asm volatile("red.global.add.v2.f32 [%0], {%1, %2};"
                         :: "l"(base + j), "f"(a), "f"(c) : "memory");
        }
    }
}

// ---------------------------------------------------------------------------
// Kernel 2: per-node update GEMM: lrelu(concat(m_sum, h_n) @ W_hid^T + b_hid)
//   Tile: 64 nodes x 224 outputs, K=224 split in 2 chunks of 112.
//   Thread layout: 256 = 16(tx: 14 outputs) x 16(ty: 4 nodes)
// ---------------------------------------------------------------------------
#define BM      64
#define KC      112
#define WHSTR   113  // (14*tx*113) % 32 = 14*tx % 32 -> distinct
#define XHSTR   116  // 16B-aligned rows, (20m+k)%32 distinct over 8 rows

#define UPD_SMEM_BYTES (((HID*WHSTR) + (BM*XHSTR) + HID) * 4)

__global__ __launch_bounds__(256, 1) void update_kernel(
    const float* __restrict__ h_n, const float* __restrict__ Wh,
    const float* __restrict__ bh, float* __restrict__ out)
{
    extern __shared__ float smem[];
    float* Wsm = smem;                     // HID * WHSTR (one K-chunk)
    float* Xsm = Wsm + HID * WHSTR;        // BM * XHSTR (one K-chunk)
    float* bsm = Xsm + BM * XHSTR;         // HID

    const int tid = threadIdx.x;
    const int r0  = blockIdx.x * BM;
    if (tid < HID) bsm[tid] = bh[tid];

    const int tx = tid & 15;
    const int ty = tid >> 4;
    const int n0 = tx * 14;

    float acc[4][14];
    #pragma unroll
    for (int m = 0; m < 4; m++)
        #pragma unroll
        for (int j = 0; j < 14; j++) acc[m][j] = 0.f;

    for (int kc = 0; kc < 2; kc++) {
        const int kbase = kc * KC;
        __syncthreads();   // protect previous chunk's smem use (and bsm on kc=0)
        // Fill W chunk: 224 rows x 28 float4
        for (int i = tid; i < HID * (KC / 4); i += 256) {
            int r = i / (KC / 4), c = (i % (KC / 4)) * 4;
            float4 v = *(const float4*)(Wh + (size_t)r * HID + kbase + c);
            float* dp = Wsm + r * WHSTR + c;
            dp[0] = v.x; dp[1] = v.y; dp[2] = v.z; dp[3] = v.w;
        }
        // Fill X chunk: concat(m_sum[row][0:160], h_n[row][0:64])
        for (int i = tid; i < BM * (KC / 4); i += 256) {
            int lr = i / (KC / 4), c = (i % (KC / 4)) * 4;
            int row = r0 + lr;
            int k = kbase + c;
            float4 v = make_float4(0.f, 0.f, 0.f, 0.f);
            if (row < N_NODES) {
                if (k < MSG) v = *(const float4*)(g_msum + (size_t)row * MSG + k);
                else         v = *(const float4*)(h_n + (size_t)row * D_NODE + (k - MSG));
            }
            *(float4*)(Xsm + lr * XHSTR + c) = v;
        }
        __syncthreads();

        const float* xb = Xsm + (ty * 4) * XHSTR;
        #pragma unroll 2
        for (int k = 0; k < KC; k++) {
            float w[14];
            #pragma unroll
            for (int j = 0; j < 14; j++) w[j] = Wsm[(n0 + j) * WHSTR + k];
            float x0 = xb[k];
            float x1 = xb[XHSTR + k];
            float x2 = xb[2 * XHSTR + k];
            float x3 = xb[3 * XHSTR + k];
            #pragma unroll
            for (int j = 0; j < 14; j++) {
                acc[0][j] = fmaf(x0, w[j], acc[0][j]);
                acc[1][j] = fmaf(x1, w[j], acc[1][j]);
                acc[2][j] = fmaf(x2, w[j], acc[2][j]);
                acc[3][j] = fmaf(x3, w[j], acc[3][j]);
            }
        }
    }

    // Epilogue: + bias, LeakyReLU, store
    #pragma unroll
    for (int m = 0; m < 4; m++) {
        int row = r0 + ty * 4 + m;
        if (row >= N_NODES) continue;
        float* op = out + (size_t)row * HID + n0;
        #pragma unroll
        for (int j = 0; j < 14; j++)
            op[j] = lrelu(acc[m][j] + bsm[n0 + j]);
    }
}

// ---------------------------------------------------------------------------
extern "C" void kernel_launch(void* const* d_in, const int* in_sizes, int n_in,
                              void* d_out, int out_size)
{
    const float* h_n = (const float*)d_in[0];
    const float* h_e = (const float*)d_in[1];
    const int*   src = (const int*)d_in[2];
    const int*   dst = (const int*)d_in[3];
    const float* Wm  = (const float*)d_in[4];
    const float* bm  = (const float*)d_in[5];
    const float* Wh  = (const float*)d_in[6];
    const float* bh  = (const float*)d_in[7];
    float* out = (float*)d_out;

    // Idempotent, capture-safe attribute sets (no allocation, no sync)
    cudaFuncSetAttribute(edge_kernel, cudaFuncAttributeMaxDynamicSharedMemorySize,
                         EDGE_SMEM_BYTES);
    cudaFuncSetAttribute(update_kernel, cudaFuncAttributeMaxDynamicSharedMemorySize,
                         UPD_SMEM_BYTES);

    zero_msum_kernel<<<2048, 256>>>();
    edge_kernel<<<(N_EDGES + BE - 1) / BE, 256, EDGE_SMEM_BYTES>>>(h_n, h_e, src, dst, Wm, bm);
    update_kernel<<<(N_NODES + BM - 1) / BM, 256, UPD_SMEM_BYTES>>>(h_n, Wh, bh, out);
}

// round 5
// speedup vs baseline: 1.8300x; 1.8300x over previous
#include <cuda_runtime.h>
#include <cuda_bf16.h>
#include <cstdint>

#define N_NODES 50000
#define N_EDGES 500000
#define D_NODE  64
#define D_EDGE  32
#define MSG     160
#define HID     224
#define ALPHA   0.01f

#define NTILES  ((N_EDGES + 127) / 128)   // 3907

// 32 MB scratch for segment-sum accumulation
__device__ float g_msum[(size_t)N_NODES * MSG];

__device__ __forceinline__ float lrelu(float v) { return v > 0.f ? v : ALPHA * v; }

__device__ __forceinline__ uint32_t smem_u32(const void* p) {
    uint32_t a;
    asm("{ .reg .u64 t; cvta.to.shared.u64 t, %1; cvt.u32.u64 %0, t; }" : "=r"(a) : "l"(p));
    return a;
}

__device__ __forceinline__ void ldsm_x4(uint32_t* r, uint32_t addr) {
    asm volatile("ldmatrix.sync.aligned.m8n8.x4.shared.b16 {%0,%1,%2,%3}, [%4];"
                 : "=r"(r[0]), "=r"(r[1]), "=r"(r[2]), "=r"(r[3]) : "r"(addr));
}

__device__ __forceinline__ void mma_bf16(float* d, const uint32_t* a,
                                         uint32_t b0, uint32_t b1) {
    asm volatile("mma.sync.aligned.m16n8k16.row.col.f32.bf16.bf16.f32 "
                 "{%0,%1,%2,%3}, {%4,%5,%6,%7}, {%8,%9}, {%0,%1,%2,%3};"
                 : "+f"(d[0]), "+f"(d[1]), "+f"(d[2]), "+f"(d[3])
                 : "r"(a[0]), "r"(a[1]), "r"(a[2]), "r"(a[3]), "r"(b0), "r"(b1));
}

// ---------------------------------------------------------------------------
// Kernel 0: zero the accumulator
// ---------------------------------------------------------------------------
__global__ void zero_msum_kernel() {
    size_t n4 = (size_t)N_NODES * MSG / 4;
    float4* p = (float4*)g_msum;
    for (size_t i = (size_t)blockIdx.x * blockDim.x + threadIdx.x; i < n4;
         i += (size_t)gridDim.x * blockDim.x)
        p[i] = make_float4(0.f, 0.f, 0.f, 0.f);
}

// ---------------------------------------------------------------------------
// Kernel 1: persistent edge kernel (mma.sync bf16-split)
//   Tile: 128 edges x 160 out, K=160. Warp w -> edge rows [16w, 16w+16).
// SMEM byte map:
//   [0,      43008)  Xhi  [128][168] bf16        (stride 168 elems = 336 B)
//   [43008,  86016)  Xlo
//   [86016, 139776)  Whi  [160][168] bf16  (row = out-feature n, col = k)
//   [139776,193536)  Wlo
//   [193536,194176)  bias (160 f32)
//   [194176,194688)  dsm  (128 i32)
//   staging (epilogue): floats [128][164] over [0, 83968)  (aliases Xhi/Xlo)
// ---------------------------------------------------------------------------
#define XSTR  168
#define WSTR  168
#define SSTR  164
#define SM_XHI   0
#define SM_XLO   43008
#define SM_WHI   86016
#define SM_WLO   139776
#define SM_BIAS  193536
#define SM_DSM   194176
#define EDGE_SMEM_BYTES 194688

__global__ __launch_bounds__(256, 1) void edge_kernel(
    const float* __restrict__ h_n, const float* __restrict__ h_e,
    const int* __restrict__ src, const int* __restrict__ dst,
    const float* __restrict__ Wm, const float* __restrict__ bm)
{
    extern __shared__ char smem[];
    const uint32_t sbase = smem_u32(smem);
    const int tid  = threadIdx.x;
    const int wid  = tid >> 5;
    const int lane = tid & 31;

    float* bsm = (float*)(smem + SM_BIAS);
    int*   dsm = (int*)(smem + SM_DSM);
    float* stg = (float*)(smem + SM_XHI);

    // --- prologue: convert W_msg to bf16 hi/lo into smem ---
    for (int i = tid; i < MSG * 40; i += 256) {
        int r = i / 40, c4 = (i % 40) * 4;
        float4 v = __ldg((const float4*)(Wm + r * MSG + c4));
        __nv_bfloat16 h0 = __float2bfloat16(v.x), h1 = __float2bfloat16(v.y);
        __nv_bfloat16 h2 = __float2bfloat16(v.z), h3 = __float2bfloat16(v.w);
        __nv_bfloat16 l0 = __float2bfloat16(v.x - __bfloat162float(h0));
        __nv_bfloat16 l1 = __float2bfloat16(v.y - __bfloat162float(h1));
        __nv_bfloat16 l2 = __float2bfloat16(v.z - __bfloat162float(h2));
        __nv_bfloat16 l3 = __float2bfloat16(v.w - __bfloat162float(h3));
        uint32_t hiA = ((uint32_t)__bfloat16_as_ushort(h1) << 16) | __bfloat16_as_ushort(h0);
        uint32_t hiB = ((uint32_t)__bfloat16_as_ushort(h3) << 16) | __bfloat16_as_ushort(h2);
        uint32_t loA = ((uint32_t)__bfloat16_as_ushort(l1) << 16) | __bfloat16_as_ushort(l0);
        uint32_t loB = ((uint32_t)__bfloat16_as_ushort(l3) << 16) | __bfloat16_as_ushort(l2);
        uint32_t off = (uint32_t)(r * WSTR + c4) * 2u;
        *(uint2*)(smem + SM_WHI + off) = make_uint2(hiA, hiB);
        *(uint2*)(smem + SM_WLO + off) = make_uint2(loA, loB);
    }
    if (tid < MSG) bsm[tid] = __ldg(bm + tid);
    __syncthreads();

    // Per-lane ldmatrix address components
    const int q  = lane >> 3;          // quadrant
    const int ri = lane & 7;
    // A quadrants: q0=(r0-7,k0) q1=(r8-15,k0) q2=(r0-7,k0+8) q3=(r8-15,k0+8)
    const uint32_t aLane = (uint32_t)(((wid * 16 + (q & 1) * 8 + ri) * XSTR +
                                       (q >> 1) * 8) * 2);
    // B quadrants: q0=(n0-7,k0) q1=(n0-7,k0+8) q2=(n8-15,k0) q3=(n8-15,k0+8)
    const uint32_t bLane = (uint32_t)((((q >> 1) * 8 + ri) * WSTR + (q & 1) * 8) * 2);

    const uint32_t aHi = sbase + SM_XHI + aLane;
    const uint32_t aLo = sbase + SM_XLO + aLane;
    const uint32_t wHi = sbase + SM_WHI + bLane;
    const uint32_t wLo = sbase + SM_WLO + bLane;

    for (int tile = blockIdx.x; tile < NTILES; tile += gridDim.x) {
        const int e0 = tile * 128;
        __syncthreads();   // S0: previous epilogue done (stg/dsm reuse)

        // --- gather + bf16 split ---
        if (tid < 128) {
            int e = e0 + tid;
            dsm[tid] = (e < N_EDGES) ? __ldg(dst + e) : -1;
        }
        for (int idx = tid; idx < 128 * 40; idx += 256) {
            int le = idx / 40, j = idx - le * 40;
            int e = e0 + le;
            float4 v = make_float4(0.f, 0.f, 0.f, 0.f);
            if (e < N_EDGES) {
                if (j < 16) {
                    int s = __ldg(src + e);
                    v = __ldg((const float4*)(h_n + (size_t)s * D_NODE) + j);
                } else if (j < 32) {
                    int d = __ldg(dst + e);
                    v = __ldg((const float4*)(h_n + (size_t)d * D_NODE) + (j - 16));
                } else {
                    v = __ldg((const float4*)(h_e + (size_t)e * D_EDGE) + (j - 32));
                }
            }
            __nv_bfloat16 h0 = __float2bfloat16(v.x), h1 = __float2bfloat16(v.y);
            __nv_bfloat16 h2 = __float2bfloat16(v.z), h3 = __float2bfloat16(v.w);
            __nv_bfloat16 l0 = __float2bfloat16(v.x - __bfloat162float(h0));
            __nv_bfloat16 l1 = __float2bfloat16(v.y - __bfloat162float(h1));
            __nv_bfloat16 l2 = __float2bfloat16(v.z - __bfloat162float(h2));
            __nv_bfloat16 l3 = __float2bfloat16(v.w - __bfloat162float(h3));
            uint32_t hiA = ((uint32_t)__bfloat16_as_ushort(h1) << 16) | __bfloat16_as_ushort(h0);
            uint32_t hiB = ((uint32_t)__bfloat16_as_ushort(h3) << 16) | __bfloat16_as_ushort(h2);
            uint32_t loA = ((uint32_t)__bfloat16_as_ushort(l1) << 16) | __bfloat16_as_ushort(l0);
            uint32_t loB = ((uint32_t)__bfloat16_as_ushort(l3) << 16) | __bfloat16_as_ushort(l2);
            uint32_t off = (uint32_t)(le * XSTR + j * 4) * 2u;
            *(uint2*)(smem + SM_XHI + off) = make_uint2(hiA, hiB);
            *(uint2*)(smem + SM_XLO + off) = make_uint2(loA, loB);
        }
        __syncthreads();   // S1: X ready

        // --- compute: acc[20 n-chunks][4] ---
        float acc[20][4];
        #pragma unroll
        for (int n = 0; n < 20; n++)
            #pragma unroll
            for (int i = 0; i < 4; i++) acc[n][i] = 0.f;

        #pragma unroll 2
        for (int kk = 0; kk < 10; kk++) {
            const uint32_t kOff = (uint32_t)(kk * 16 * 2);
            uint32_t Ahi[4], Alo[4];
            ldsm_x4(Ahi, aHi + kOff);
            ldsm_x4(Alo, aLo + kOff);
            #pragma unroll
            for (int np = 0; np < 10; np++) {
                const uint32_t nOff = (uint32_t)(np * 16 * WSTR * 2) + kOff;
                uint32_t Bhi[4], Blo[4];
                ldsm_x4(Bhi, wHi + nOff);
                ldsm_x4(Blo, wLo + nOff);
                mma_bf16(acc[np * 2],     Ahi, Bhi[0], Bhi[1]);
                mma_bf16(acc[np * 2],     Ahi, Blo[0], Blo[1]);
                mma_bf16(acc[np * 2],     Alo, Bhi[0], Bhi[1]);
                mma_bf16(acc[np * 2 + 1], Ahi, Bhi[2], Bhi[3]);
                mma_bf16(acc[np * 2 + 1], Ahi, Blo[2], Blo[3]);
                mma_bf16(acc[np * 2 + 1], Alo, Bhi[2], Bhi[3]);
            }
        }
        __syncthreads();   // S2: all warps done reading X before staging write

        // --- stage accumulators to smem (rows x 164 f32) ---
        {
            const int r0 = wid * 16 + (lane >> 2);
            const int r1 = r0 + 8;
            const int cb = (lane & 3) * 2;
            #pragma unroll
            for (int n = 0; n < 20; n++) {
                *(float2*)(stg + r0 * SSTR + n * 8 + cb) = make_float2(acc[n][0], acc[n][1]);
                *(float2*)(stg + r1 * SSTR + n * 8 + cb) = make_float2(acc[n][2], acc[n][3]);
            }
        }
        __syncthreads();   // S3: staging complete

        // --- bias + lrelu + red.v4 scatter ---
        for (int i = tid; i < 128 * 40; i += 256) {
            int row = i / 40, cg = (i - row * 40) * 4;
            int d = dsm[row];
            if (d < 0) continue;
            float4 v = *(float4*)(stg + row * SSTR + cg);
            v.x = lrelu(v.x + bsm[cg]);
            v.y = lrelu(v.y + bsm[cg + 1]);
            v.z = lrelu(v.z + bsm[cg + 2]);
            v.w = lrelu(v.w + bsm[cg + 3]);
            asm volatile("red.global.add.v4.f32 [%0], {%1, %2, %3, %4};"
                         :: "l"(g_msum + (size_t)d * MSG + cg),
                            "f"(v.x), "f"(v.y), "f"(v.z), "f"(v.w) : "memory");
        }
    }
}

// ---------------------------------------------------------------------------
// Kernel 2: per-node update GEMM (fp32, validated R1 version)
// ---------------------------------------------------------------------------
#define BM      64
#define KC      112
#define WHSTR   113
#define XHSTR   116
#define UPD_SMEM_BYTES (((HID*WHSTR) + (BM*XHSTR) + HID) * 4)

__global__ __launch_bounds__(256, 1) void update_kernel(
    const float* __restrict__ h_n, const float* __restrict__ Wh,
    const float* __restrict__ bh, float* __restrict__ out)
{
    extern __shared__ float smemf[];
    float* Wsm = smemf;
    float* Xsm = Wsm + HID * WHSTR;
    float* bsm = Xsm + BM * XHSTR;

    const int tid = threadIdx.x;
    const int r0  = blockIdx.x * BM;
    if (tid < HID) bsm[tid] = bh[tid];

    const int tx = tid & 15;
    const int ty = tid >> 4;
    const int n0 = tx * 14;

    float acc[4][14];
    #pragma unroll
    for (int m = 0; m < 4; m++)
        #pragma unroll
        for (int j = 0; j < 14; j++) acc[m][j] = 0.f;

    for (int kc = 0; kc < 2; kc++) {
        const int kbase = kc * KC;
        __syncthreads();
        for (int i = tid; i < HID * (KC / 4); i += 256) {
            int r = i / (KC / 4), c = (i % (KC / 4)) * 4;
            float4 v = *(const float4*)(Wh + (size_t)r * HID + kbase + c);
            float* dp = Wsm + r * WHSTR + c;
            dp[0] = v.x; dp[1] = v.y; dp[2] = v.z; dp[3] = v.w;
        }
        for (int i = tid; i < BM * (KC / 4); i += 256) {
            int lr = i / (KC / 4), c = (i % (KC / 4)) * 4;
            int row = r0 + lr;
            int k = kbase + c;
            float4 v = make_float4(0.f, 0.f, 0.f, 0.f);
            if (row < N_NODES) {
                if (k < MSG) v = *(const float4*)(g_msum + (size_t)row * MSG + k);
                else         v = *(const float4*)(h_n + (size_t)row * D_NODE + (k - MSG));
            }
            *(float4*)(Xsm + lr * XHSTR + c) = v;
        }
        __syncthreads();

        const float* xb = Xsm + (ty * 4) * XHSTR;
        #pragma unroll 2
        for (int k = 0; k < KC; k++) {
            float w[14];
            #pragma unroll
            for (int j = 0; j < 14; j++) w[j] = Wsm[(n0 + j) * WHSTR + k];
            float x0 = xb[k];
            float x1 = xb[XHSTR + k];
            float x2 = xb[2 * XHSTR + k];
            float x3 = xb[3 * XHSTR + k];
            #pragma unroll
            for (int j = 0; j < 14; j++) {
                acc[0][j] = fmaf(x0, w[j], acc[0][j]);
                acc[1][j] = fmaf(x1, w[j], acc[1][j]);
                acc[2][j] = fmaf(x2, w[j], acc[2][j]);
                acc[3][j] = fmaf(x3, w[j], acc[3][j]);
            }
        }
    }

    #pragma unroll
    for (int m = 0; m < 4; m++) {
        int row = r0 + ty * 4 + m;
        if (row >= N_NODES) continue;
        float* op = out + (size_t)row * HID + n0;
        #pragma unroll
        for (int j = 0; j < 14; j++)
            op[j] = lrelu(acc[m][j] + bsm[n0 + j]);
    }
}

// ---------------------------------------------------------------------------
extern "C" void kernel_launch(void* const* d_in, const int* in_sizes, int n_in,
                              void* d_out, int out_size)
{
    const float* h_n = (const float*)d_in[0];
    const float* h_e = (const float*)d_in[1];
    const int*   src = (const int*)d_in[2];
    const int*   dst = (const int*)d_in[3];
    const float* Wm  = (const float*)d_in[4];
    const float* bm  = (const float*)d_in[5];
    const float* Wh  = (const float*)d_in[6];
    const float* bh  = (const float*)d_in[7];
    float* out = (float*)d_out;

    cudaFuncSetAttribute(edge_kernel, cudaFuncAttributeMaxDynamicSharedMemorySize,
                         EDGE_SMEM_BYTES);
    cudaFuncSetAttribute(update_kernel, cudaFuncAttributeMaxDynamicSharedMemorySize,
                         UPD_SMEM_BYTES);

    zero_msum_kernel<<<2048, 256>>>();
    edge_kernel<<<152, 256, EDGE_SMEM_BYTES>>>(h_n, h_e, src, dst, Wm, bm);
    update_kernel<<<(N_NODES + BM - 1) / BM, 256, UPD_SMEM_BYTES>>>(h_n, Wh, bh, out);
}

// round 7
// speedup vs baseline: 2.9576x; 1.6162x over previous
#include <cuda_runtime.h>
#include <cuda_bf16.h>
#include <cstdint>

#define N_NODES 50000
#define N_EDGES 500000
#define D_NODE  64
#define D_EDGE  32
#define MSG     160
#define HID     224
#define ALPHA   0.01f

#define NTILES  ((N_EDGES + 127) / 128)   // 3907

// 32 MB scratch for segment-sum accumulation
__device__ float g_msum[(size_t)N_NODES * MSG];

__device__ __forceinline__ float lrelu(float v) { return v > 0.f ? v : ALPHA * v; }

__device__ __forceinline__ uint32_t smem_u32(const void* p) {
    uint32_t a;
    asm("{ .reg .u64 t; cvta.to.shared.u64 t, %1; cvt.u32.u64 %0, t; }" : "=r"(a) : "l"(p));
    return a;
}

__device__ __forceinline__ void ldsm_x4(uint32_t* r, uint32_t addr) {
    asm volatile("ldmatrix.sync.aligned.m8n8.x4.shared.b16 {%0,%1,%2,%3}, [%4];"
                 : "=r"(r[0]), "=r"(r[1]), "=r"(r[2]), "=r"(r[3]) : "r"(addr));
}

__device__ __forceinline__ void mma_bf16(float* d, const uint32_t* a,
                                         uint32_t b0, uint32_t b1) {
    asm volatile("mma.sync.aligned.m16n8k16.row.col.f32.bf16.bf16.f32 "
                 "{%0,%1,%2,%3}, {%4,%5,%6,%7}, {%8,%9}, {%0,%1,%2,%3};"
                 : "+f"(d[0]), "+f"(d[1]), "+f"(d[2]), "+f"(d[3])
                 : "r"(a[0]), "r"(a[1]), "r"(a[2]), "r"(a[3]), "r"(b0), "r"(b1));
}

// pack a float4 into hi/lo bf16x2 pairs
__device__ __forceinline__ void split4(float4 v, uint2& hi, uint2& lo) {
    __nv_bfloat16 h0 = __float2bfloat16(v.x), h1 = __float2bfloat16(v.y);
    __nv_bfloat16 h2 = __float2bfloat16(v.z), h3 = __float2bfloat16(v.w);
    __nv_bfloat16 l0 = __float2bfloat16(v.x - __bfloat162float(h0));
    __nv_bfloat16 l1 = __float2bfloat16(v.y - __bfloat162float(h1));
    __nv_bfloat16 l2 = __float2bfloat16(v.z - __bfloat162float(h2));
    __nv_bfloat16 l3 = __float2bfloat16(v.w - __bfloat162float(h3));
    hi.x = ((uint32_t)__bfloat16_as_ushort(h1) << 16) | __bfloat16_as_ushort(h0);
    hi.y = ((uint32_t)__bfloat16_as_ushort(h3) << 16) | __bfloat16_as_ushort(h2);
    lo.x = ((uint32_t)__bfloat16_as_ushort(l1) << 16) | __bfloat16_as_ushort(l0);
    lo.y = ((uint32_t)__bfloat16_as_ushort(l3) << 16) | __bfloat16_as_ushort(l2);
}

// ---------------------------------------------------------------------------
// Kernel 0: zero the accumulator
// ---------------------------------------------------------------------------
__global__ void zero_msum_kernel() {
    size_t n4 = (size_t)N_NODES * MSG / 4;
    float4* p = (float4*)g_msum;
    for (size_t i = (size_t)blockIdx.x * blockDim.x + threadIdx.x; i < n4;
         i += (size_t)gridDim.x * blockDim.x)
        p[i] = make_float4(0.f, 0.f, 0.f, 0.f);
}

// ---------------------------------------------------------------------------
// Kernel 1: persistent edge kernel (mma.sync bf16-split), 512 threads
//   Tile: 128 edges x 160 out, K=160.
//   16 warps = 8 m-chunks (16 edges) x 2 n-halves (80 outs)
// ---------------------------------------------------------------------------
#define XSTR  168
#define WSTR  168
#define SSTR  164
#define SM_XHI   0
#define SM_XLO   43008
#define SM_WHI   86016
#define SM_WLO   139776
#define SM_BIAS  193536
#define SM_DSM   194176
#define EDGE_SMEM_BYTES 194688

__global__ __launch_bounds__(512, 1) void edge_kernel(
    const float* __restrict__ h_n, const float* __restrict__ h_e,
    const int* __restrict__ src, const int* __restrict__ dst,
    const float* __restrict__ Wm, const float* __restrict__ bm)
{
    extern __shared__ char smem[];
    const uint32_t sbase = smem_u32(smem);
    const int tid  = threadIdx.x;
    const int wid  = tid >> 5;
    const int lane = tid & 31;

    float* bsm = (float*)(smem + SM_BIAS);
    int*   dsm = (int*)(smem + SM_DSM);
    float* stg = (float*)(smem + SM_XHI);

    // --- prologue: convert W_msg to bf16 hi/lo into smem ---
    for (int i = tid; i < MSG * 40; i += 512) {
        int r = i / 40, c4 = (i % 40) * 4;
        float4 v = __ldg((const float4*)(Wm + r * MSG + c4));
        uint2 hi, lo; split4(v, hi, lo);
        uint32_t off = (uint32_t)(r * WSTR + c4) * 2u;
        *(uint2*)(smem + SM_WHI + off) = hi;
        *(uint2*)(smem + SM_WLO + off) = lo;
    }
    if (tid < MSG) bsm[tid] = __ldg(bm + tid);
    __syncthreads();

    const int q  = lane >> 3;
    const int ri = lane & 7;
    const int mchunk = wid & 7;       // 16-edge row group
    const int nhalf  = wid >> 3;      // 80-output column half
    // A quadrants: (r, k): q0=(+0,+0) q1=(+8,+0) q2=(+0,+8) q3=(+8,+8)
    const uint32_t aLane = (uint32_t)(((mchunk * 16 + (q & 1) * 8 + ri) * XSTR +
                                       (q >> 1) * 8) * 2);
    // B quadrants: (n, k): q0=(+0,+0) q1=(+0,+8) q2=(+8,+0) q3=(+8,+8)
    const uint32_t bLane = (uint32_t)(((nhalf * 80 + (q >> 1) * 8 + ri) * WSTR +
                                       (q & 1) * 8) * 2);

    const uint32_t aHi = sbase + SM_XHI + aLane;
    const uint32_t aLo = sbase + SM_XLO + aLane;
    const uint32_t wHi = sbase + SM_WHI + bLane;
    const uint32_t wLo = sbase + SM_WLO + bLane;

    for (int tile = blockIdx.x; tile < NTILES; tile += gridDim.x) {
        const int e0 = tile * 128;
        __syncthreads();   // previous epilogue done (stg/dsm reuse)

        // --- gather + bf16 split ---
        if (tid < 128) {
            int e = e0 + tid;
            dsm[tid] = (e < N_EDGES) ? __ldg(dst + e) : -1;
        }
        for (int idx = tid; idx < 128 * 40; idx += 512) {
            int le = idx / 40, j = idx - le * 40;
            int e = e0 + le;
            float4 v = make_float4(0.f, 0.f, 0.f, 0.f);
            if (e < N_EDGES) {
                if (j < 16) {
                    int s = __ldg(src + e);
                    v = __ldg((const float4*)(h_n + (size_t)s * D_NODE) + j);
                } else if (j < 32) {
                    int d = __ldg(dst + e);
                    v = __ldg((const float4*)(h_n + (size_t)d * D_NODE) + (j - 16));
                } else {
                    v = __ldg((const float4*)(h_e + (size_t)e * D_EDGE) + (j - 32));
                }
            }
            uint2 hi, lo; split4(v, hi, lo);
            uint32_t off = (uint32_t)(le * XSTR + j * 4) * 2u;
            *(uint2*)(smem + SM_XHI + off) = hi;
            *(uint2*)(smem + SM_XLO + off) = lo;
        }
        __syncthreads();   // X ready

        // --- compute: warp covers 16 edges x 80 outs: acc[10 n8][4] ---
        float acc[10][4];
        #pragma unroll
        for (int n = 0; n < 10; n++)
            #pragma unroll
            for (int i = 0; i < 4; i++) acc[n][i] = 0.f;

        #pragma unroll 2
        for (int kk = 0; kk < 10; kk++) {
            const uint32_t kOff = (uint32_t)(kk * 32);
            uint32_t Ahi[4], Alo[4];
            ldsm_x4(Ahi, aHi + kOff);
            ldsm_x4(Alo, aLo + kOff);
            #pragma unroll
            for (int np = 0; np < 5; np++) {
                const uint32_t nOff = (uint32_t)(np * 16 * WSTR * 2) + kOff;
                uint32_t Bhi[4], Blo[4];
                ldsm_x4(Bhi, wHi + nOff);
                ldsm_x4(Blo, wLo + nOff);
                mma_bf16(acc[np * 2],     Ahi, Bhi[0], Bhi[1]);
                mma_bf16(acc[np * 2],     Ahi, Blo[0], Blo[1]);
                mma_bf16(acc[np * 2],     Alo, Bhi[0], Bhi[1]);
                mma_bf16(acc[np * 2 + 1], Ahi, Bhi[2], Bhi[3]);
                mma_bf16(acc[np * 2 + 1], Ahi, Blo[2], Blo[3]);
                mma_bf16(acc[np * 2 + 1], Alo, Bhi[2], Bhi[3]);
            }
        }
        __syncthreads();   // all warps done reading X before staging write

        // --- stage accumulators to smem [128][164] f32 ---
        {
            const int r0 = mchunk * 16 + (lane >> 2);
            const int r1 = r0 + 8;
            const int cb = nhalf * 80 + (lane & 3) * 2;
            #pragma unroll
            for (int n = 0; n < 10; n++) {
                *(float2*)(stg + r0 * SSTR + cb + n * 8) = make_float2(acc[n][0], acc[n][1]);
                *(float2*)(stg + r1 * SSTR + cb + n * 8) = make_float2(acc[n][2], acc[n][3]);
            }
        }
        __syncthreads();   // staging complete

        // --- bias + lrelu + red.v4 scatter ---
        for (int i = tid; i < 128 * 40; i += 512) {
            int row = i / 40, cg = (i - row * 40) * 4;
            int d = dsm[row];
            if (d < 0) continue;
            float4 v = *(float4*)(stg + row * SSTR + cg);
            v.x = lrelu(v.x + bsm[cg]);
            v.y = lrelu(v.y + bsm[cg + 1]);
            v.z = lrelu(v.z + bsm[cg + 2]);
            v.w = lrelu(v.w + bsm[cg + 3]);
            asm volatile("red.global.add.v4.f32 [%0], {%1, %2, %3, %4};"
                         :: "l"(g_msum + (size_t)d * MSG + cg),
                            "f"(v.x), "f"(v.y), "f"(v.z), "f"(v.w) : "memory");
        }
    }
}

// ---------------------------------------------------------------------------
// Kernel 2: update GEMM via mma.sync bf16-split, 512 threads
//   Tile: 128 nodes x 224 out, K=224 in 2 chunks of 112.
//   16 warps = 8 m-chunks x 2 n-halves (112 outs each)
// SMEM: XHI [128][120]bf16, XLO, WHI [224][120]bf16, WLO, bias[224]
// ---------------------------------------------------------------------------
#define UXSTR 120
#define UWSTR 120
#define USM_XHI  0
#define USM_XLO  30720
#define USM_WHI  61440
#define USM_WLO  115200
#define USM_BIAS 168960
#define UPD_SMEM_BYTES 169856

__global__ __launch_bounds__(512, 1) void update_kernel(
    const float* __restrict__ h_n, const float* __restrict__ Wh,
    const float* __restrict__ bh, float* __restrict__ out)
{
    extern __shared__ char smem[];
    const uint32_t sbase = smem_u32(smem);
    const int tid  = threadIdx.x;
    const int wid  = tid >> 5;
    const int lane = tid & 31;
    const int r0g  = blockIdx.x * 128;

    float* bsm = (float*)(smem + USM_BIAS);
    if (tid < HID) bsm[tid] = __ldg(bh + tid);

    const int q  = lane >> 3;
    const int ri = lane & 7;
    const int mchunk = wid & 7;
    const int nhalf  = wid >> 3;

    const uint32_t aLane = (uint32_t)(((mchunk * 16 + (q & 1) * 8 + ri) * UXSTR +
                                       (q >> 1) * 8) * 2);
    const uint32_t bLane = (uint32_t)(((nhalf * 112 + (q >> 1) * 8 + ri) * UWSTR +
                                       (q & 1) * 8) * 2);
    const uint32_t aHi = sbase + USM_XHI + aLane;
    const uint32_t aLo = sbase + USM_XLO + aLane;
    const uint32_t wHi = sbase + USM_WHI + bLane;
    const uint32_t wLo = sbase + USM_WLO + bLane;

    float acc[14][4];
    #pragma unroll
    for (int n = 0; n < 14; n++)
        #pragma unroll
        for (int i = 0; i < 4; i++) acc[n][i] = 0.f;

    for (int kc = 0; kc < 2; kc++) {
        const int kbase = kc * 112;
        __syncthreads();   // previous chunk mma done (and bsm written on kc=0)

        // W chunk: 224 rows x 28 float4
        for (int i = tid; i < HID * 28; i += 512) {
            int r = i / 28, c4 = (i % 28) * 4;
            float4 v = __ldg((const float4*)(Wh + (size_t)r * HID + kbase + c4));
            uint2 hi, lo; split4(v, hi, lo);
            uint32_t off = (uint32_t)(r * UWSTR + c4) * 2u;
            *(uint2*)(smem + USM_WHI + off) = hi;
            *(uint2*)(smem + USM_WLO + off) = lo;
        }
        // X chunk: concat(m_sum, h_n) cols [kbase, kbase+112)
        for (int i = tid; i < 128 * 28; i += 512) {
            int lr = i / 28, c4 = (i % 28) * 4;
            int row = r0g + lr;
            int kg = kbase + c4;
            float4 v = make_float4(0.f, 0.f, 0.f, 0.f);
            if (row < N_NODES) {
                if (kg < MSG) v = *(const float4*)(g_msum + (size_t)row * MSG + kg);
                else          v = *(const float4*)(h_n + (size_t)row * D_NODE + (kg - MSG));
            }
            uint2 hi, lo; split4(v, hi, lo);
            uint32_t off = (uint32_t)(lr * UXSTR + c4) * 2u;
            *(uint2*)(smem + USM_XHI + off) = hi;
            *(uint2*)(smem + USM_XLO + off) = lo;
        }
        __syncthreads();

        #pragma unroll 1
        for (int kk = 0; kk < 7; kk++) {
            const uint32_t kOff = (uint32_t)(kk * 32);
            uint32_t Ahi[4], Alo[4];
            ldsm_x4(Ahi, aHi + kOff);
            ldsm_x4(Alo, aLo + kOff);
            #pragma unroll
            for (int np = 0; np < 7; np++) {
                const uint32_t nOff = (uint32_t)(np * 16 * UWSTR * 2) + kOff;
                uint32_t Bhi[4], Blo[4];
                ldsm_x4(Bhi, wHi + nOff);
                ldsm_x4(Blo, wLo + nOff);
                mma_bf16(acc[np * 2],     Ahi, Bhi[0], Bhi[1]);
                mma_bf16(acc[np * 2],     Ahi, Blo[0], Blo[1]);
                mma_bf16(acc[np * 2],     Alo, Bhi[0], Bhi[1]);
                mma_bf16(acc[np * 2 + 1], Ahi, Bhi[2], Bhi[3]);
                mma_bf16(acc[np * 2 + 1], Ahi, Blo[2], Blo[3]);
                mma_bf16(acc[np * 2 + 1], Alo, Bhi[2], Bhi[3]);
            }
        }
    }

    // --- epilogue: bias + lrelu + direct STG.64 ---
    {
        const int rA = r0g + mchunk * 16 + (lane >> 2);
        const int rB = rA + 8;
        const int cb = nhalf * 112 + (lane & 3) * 2;
        #pragma unroll
        for (int n = 0; n < 14; n++) {
            int c = cb + n * 8;
            float b0 = bsm[c], b1 = bsm[c + 1];
            if (rA < N_NODES) {
                float2 v = make_float2(lrelu(acc[n][0] + b0), lrelu(acc[n][1] + b1));
                *(float2*)(out + (size_t)rA * HID + c) = v;
            }
            if (rB < N_NODES) {
                float2 v = make_float2(lrelu(acc[n][2] + b0), lrelu(acc[n][3] + b1));
                *(float2*)(out + (size_t)rB * HID + c) = v;
            }
        }
    }
}

// ---------------------------------------------------------------------------
extern "C" void kernel_launch(void* const* d_in, const int* in_sizes, int n_in,
                              void* d_out, int out_size)
{
    const float* h_n = (const float*)d_in[0];
    const float* h_e = (const float*)d_in[1];
    const int*   src = (const int*)d_in[2];
    const int*   dst = (const int*)d_in[3];
    const float* Wm  = (const float*)d_in[4];
    const float* bm  = (const float*)d_in[5];
    const float* Wh  = (const float*)d_in[6];
    const float* bh  = (const float*)d_in[7];
    float* out = (float*)d_out;

    cudaFuncSetAttribute(edge_kernel, cudaFuncAttributeMaxDynamicSharedMemorySize,
                         EDGE_SMEM_BYTES);
    cudaFuncSetAttribute(update_kernel, cudaFuncAttributeMaxDynamicSharedMemorySize,
                         UPD_SMEM_BYTES);

    zero_msum_kernel<<<2048, 256>>>();
    edge_kernel<<<152, 512, EDGE_SMEM_BYTES>>>(h_n, h_e, src, dst, Wm, bm);
    update_kernel<<<(N_NODES + 127) / 128, 512, UPD_SMEM_BYTES>>>(h_n, Wh, bh, out);
}

// round 9
// speedup vs baseline: 3.6742x; 1.2423x over previous
#include <cuda_runtime.h>
#include <cuda_bf16.h>
#include <cstdint>

#define N_NODES 50000
#define N_EDGES 500000
#define D_NODE  64
#define D_EDGE  32
#define MSG     160
#define HID     224
#define ALPHA   0.01f

#define NTILES  ((N_EDGES + 127) / 128)   // 3907

// 32 MB scratch for segment-sum accumulation
__device__ float g_msum[(size_t)N_NODES * MSG];

__device__ __forceinline__ float lrelu(float v) { return v > 0.f ? v : ALPHA * v; }

__device__ __forceinline__ uint32_t smem_u32(const void* p) {
    uint32_t a;
    asm("{ .reg .u64 t; cvta.to.shared.u64 t, %1; cvt.u32.u64 %0, t; }" : "=r"(a) : "l"(p));
    return a;
}

__device__ __forceinline__ void ldsm_x4(uint32_t* r, uint32_t addr) {
    asm volatile("ldmatrix.sync.aligned.m8n8.x4.shared.b16 {%0,%1,%2,%3}, [%4];"
                 : "=r"(r[0]), "=r"(r[1]), "=r"(r[2]), "=r"(r[3]) : "r"(addr));
}

__device__ __forceinline__ void mma_bf16(float* d, const uint32_t* a,
                                         uint32_t b0, uint32_t b1) {
    asm volatile("mma.sync.aligned.m16n8k16.row.col.f32.bf16.bf16.f32 "
                 "{%0,%1,%2,%3}, {%4,%5,%6,%7}, {%8,%9}, {%0,%1,%2,%3};"
                 : "+f"(d[0]), "+f"(d[1]), "+f"(d[2]), "+f"(d[3])
                 : "r"(a[0]), "r"(a[1]), "r"(a[2]), "r"(a[3]), "r"(b0), "r"(b1));
}

// pack a float4 into hi/lo bf16x2 pairs
__device__ __forceinline__ void split4(float4 v, uint2& hi, uint2& lo) {
    __nv_bfloat16 h0 = __float2bfloat16(v.x), h1 = __float2bfloat16(v.y);
    __nv_bfloat16 h2 = __float2bfloat16(v.z), h3 = __float2bfloat16(v.w);
    __nv_bfloat16 l0 = __float2bfloat16(v.x - __bfloat162float(h0));
    __nv_bfloat16 l1 = __float2bfloat16(v.y - __bfloat162float(h1));
    __nv_bfloat16 l2 = __float2bfloat16(v.z - __bfloat162float(h2));
    __nv_bfloat16 l3 = __float2bfloat16(v.w - __bfloat162float(h3));
    hi.x = ((uint32_t)__bfloat16_as_ushort(h1) << 16) | __bfloat16_as_ushort(h0);
    hi.y = ((uint32_t)__bfloat16_as_ushort(h3) << 16) | __bfloat16_as_ushort(h2);
    lo.x = ((uint32_t)__bfloat16_as_ushort(l1) << 16) | __bfloat16_as_ushort(l0);
    lo.y = ((uint32_t)__bfloat16_as_ushort(l3) << 16) | __bfloat16_as_ushort(l2);
}

// ---------------------------------------------------------------------------
// Kernel 0: zero the accumulator
// ---------------------------------------------------------------------------
__global__ void zero_msum_kernel() {
    size_t n4 = (size_t)N_NODES * MSG / 4;
    float4* p = (float4*)g_msum;
    for (size_t i = (size_t)blockIdx.x * blockDim.x + threadIdx.x; i < n4;
         i += (size_t)gridDim.x * blockDim.x)
        p[i] = make_float4(0.f, 0.f, 0.f, 0.f);
}

// ---------------------------------------------------------------------------
// Kernel 1: persistent edge kernel (mma.sync bf16-split), 512 threads
//   Tile: 128 edges x 160 out, K=160.
//   16 warps = 8 m-chunks (16 edges) x 2 n-halves (80 outs)
//   2 syncs/tile; scatter direct from regs via shfl-built v4.
// ---------------------------------------------------------------------------
#define XSTR  168
#define WSTR  168
#define SM_XHI   0
#define SM_XLO   43008
#define SM_WHI   86016
#define SM_WLO   139776
#define SM_BIAS  193536
#define SM_DSM   194176
#define EDGE_SMEM_BYTES 194688

__global__ __launch_bounds__(512, 1) void edge_kernel(
    const float* __restrict__ h_n, const float* __restrict__ h_e,
    const int* __restrict__ src, const int* __restrict__ dst,
    const float* __restrict__ Wm, const float* __restrict__ bm)
{
    extern __shared__ char smem[];
    const uint32_t sbase = smem_u32(smem);
    const int tid  = threadIdx.x;
    const int wid  = tid >> 5;
    const int lane = tid & 31;

    float* bsm = (float*)(smem + SM_BIAS);
    int*   dsm = (int*)(smem + SM_DSM);

    // --- prologue: convert W_msg to bf16 hi/lo into smem ---
    for (int i = tid; i < MSG * 40; i += 512) {
        int r = i / 40, c4 = (i % 40) * 4;
        float4 v = __ldg((const float4*)(Wm + r * MSG + c4));
        uint2 hi, lo; split4(v, hi, lo);
        uint32_t off = (uint32_t)(r * WSTR + c4) * 2u;
        *(uint2*)(smem + SM_WHI + off) = hi;
        *(uint2*)(smem + SM_WLO + off) = lo;
    }
    if (tid < MSG) bsm[tid] = __ldg(bm + tid);
    __syncthreads();

    const int q  = lane >> 3;
    const int ri = lane & 7;
    const int mchunk = wid & 7;       // 16-edge row group
    const int nhalf  = wid >> 3;      // 80-output column half
    // A quadrants: (r, k): q0=(+0,+0) q1=(+8,+0) q2=(+0,+8) q3=(+8,+8)
    const uint32_t aLane = (uint32_t)(((mchunk * 16 + (q & 1) * 8 + ri) * XSTR +
                                       (q >> 1) * 8) * 2);
    // B quadrants: (n, k): q0=(+0,+0) q1=(+0,+8) q2=(+8,+0) q3=(+8,+8)
    const uint32_t bLane = (uint32_t)(((nhalf * 80 + (q >> 1) * 8 + ri) * WSTR +
                                       (q & 1) * 8) * 2);

    const uint32_t aHi = sbase + SM_XHI + aLane;
    const uint32_t aLo = sbase + SM_XLO + aLane;
    const uint32_t wHi = sbase + SM_WHI + bLane;
    const uint32_t wLo = sbase + SM_WLO + bLane;

    // gather mapping: 4 threads per edge, 10 float4 each
    const int gle = tid >> 2;          // edge slot 0..127
    const int gj0 = (tid & 3) * 10;    // first float4 index

    for (int tile = blockIdx.x; tile < NTILES; tile += gridDim.x) {
        const int e0 = tile * 128;
        __syncthreads();   // prev tile's compute done; REDGs drain in background

        // --- gather + bf16 split ---
        if (tid < 128) {
            int e = e0 + tid;
            dsm[tid] = (e < N_EDGES) ? __ldg(dst + e) : -1;
        }
        {
            const int e = e0 + gle;
            const bool valid = (e < N_EDGES);
            int s = 0, d = 0;
            if (valid) { s = __ldg(src + e); d = __ldg(dst + e); }
            const float4* ps = (const float4*)(h_n + (size_t)s * D_NODE);
            const float4* pd = (const float4*)(h_n + (size_t)d * D_NODE);
            const float4* pe = (const float4*)(h_e + (size_t)e * D_EDGE);
            #pragma unroll
            for (int i = 0; i < 10; i++) {
                const int j = gj0 + i;
                float4 v = make_float4(0.f, 0.f, 0.f, 0.f);
                if (valid) {
                    if (j < 16)      v = __ldg(ps + j);
                    else if (j < 32) v = __ldg(pd + (j - 16));
                    else             v = __ldg(pe + (j - 32));
                }
                uint2 hi, lo; split4(v, hi, lo);
                uint32_t off = (uint32_t)(gle * XSTR + j * 4) * 2u;
                *(uint2*)(smem + SM_XHI + off) = hi;
                *(uint2*)(smem + SM_XLO + off) = lo;
            }
        }
        __syncthreads();   // X ready

        // --- compute: warp covers 16 edges x 80 outs: acc[10 n8][4] ---
        float acc[10][4];
        #pragma unroll
        for (int n = 0; n < 10; n++)
            #pragma unroll
            for (int i = 0; i < 4; i++) acc[n][i] = 0.f;

        #pragma unroll 2
        for (int kk = 0; kk < 10; kk++) {
            const uint32_t kOff = (uint32_t)(kk * 32);
            uint32_t Ahi[4], Alo[4];
            ldsm_x4(Ahi, aHi + kOff);
            ldsm_x4(Alo, aLo + kOff);
            #pragma unroll
            for (int np = 0; np < 5; np++) {
                const uint32_t nOff = (uint32_t)(np * 16 * WSTR * 2) + kOff;
                uint32_t Bhi[4], Blo[4];
                ldsm_x4(Bhi, wHi + nOff);
                ldsm_x4(Blo, wLo + nOff);
                mma_bf16(acc[np * 2],     Ahi, Bhi[0], Bhi[1]);
                mma_bf16(acc[np * 2],     Ahi, Blo[0], Blo[1]);
                mma_bf16(acc[np * 2],     Alo, Bhi[0], Bhi[1]);
                mma_bf16(acc[np * 2 + 1], Ahi, Bhi[2], Bhi[3]);
                mma_bf16(acc[np * 2 + 1], Ahi, Blo[2], Blo[3]);
                mma_bf16(acc[np * 2 + 1], Alo, Bhi[2], Bhi[3]);
            }
        }

        // --- epilogue: shfl pairs into v4, bias + lrelu + red.v4 scatter ---
        {
            const int g  = lane & 3;
            const int r0 = mchunk * 16 + (lane >> 2);
            const int d0 = dsm[r0];
            const int d1 = dsm[r0 + 8];
            const int cb = nhalf * 80;
            #pragma unroll
            for (int t = 0; t < 5; t++) {
                const int n0 = 2 * t, n1 = 2 * t + 1;
                #pragma unroll
                for (int h = 0; h < 2; h++) {
                    // own pairs: p(n0) = cols {2g,2g+1} of n0-block; p(n1) likewise
                    float ox0 = acc[n0][2 * h], ox1 = acc[n0][2 * h + 1];
                    float oy0 = acc[n1][2 * h], oy1 = acc[n1][2 * h + 1];
                    // odd g sends its n0 pair, even g sends its n1 pair (bfly mask 1)
                    float s0 = (g & 1) ? ox0 : oy0;
                    float s1 = (g & 1) ? ox1 : oy1;
                    float rc0 = __shfl_xor_sync(0xffffffffu, s0, 1);
                    float rc1 = __shfl_xor_sync(0xffffffffu, s1, 1);
                    // even g: v4 = (own n0 pair, recv n0 pair of g^1)
                    // odd  g: v4 = (recv n1 pair of g^1, own n1 pair)
                    float v0, v1, v2, v3;
                    if (g & 1) { v0 = rc0; v1 = rc1; v2 = oy0; v3 = oy1; }
                    else       { v0 = ox0; v1 = ox1; v2 = rc0; v3 = rc1; }
                    const int c = cb + ((g & 1) ? n1 : n0) * 8 + (g & 2) * 2;
                    const int d = h ? d1 : d0;
                    if (d >= 0) {
                        float4 b = *(const float4*)(bsm + c);
                        v0 = lrelu(v0 + b.x); v1 = lrelu(v1 + b.y);
                        v2 = lrelu(v2 + b.z); v3 = lrelu(v3 + b.w);
                        asm volatile("red.global.add.v4.f32 [%0], {%1, %2, %3, %4};"
                                     :: "l"(g_msum + (size_t)d * MSG + c),
                                        "f"(v0), "f"(v1), "f"(v2), "f"(v3) : "memory");
                    }
                }
            }
        }
    }
}

// ---------------------------------------------------------------------------
// Kernel 2: update GEMM via mma.sync bf16-split, 512 threads (validated R7)
// ---------------------------------------------------------------------------
#define UXSTR 120
#define UWSTR 120
#define USM_XHI  0
#define USM_XLO  30720
#define USM_WHI  61440
#define USM_WLO  115200
#define USM_BIAS 168960
#define UPD_SMEM_BYTES 169856

__global__ __launch_bounds__(512, 1) void update_kernel(
    const float* __restrict__ h_n, const float* __restrict__ Wh,
    const float* __restrict__ bh, float* __restrict__ out)
{
    extern __shared__ char smem[];
    const uint32_t sbase = smem_u32(smem);
    const int tid  = threadIdx.x;
    const int wid  = tid >> 5;
    const int lane = tid & 31;
    const int r0g  = blockIdx.x * 128;

    float* bsm = (float*)(smem + USM_BIAS);
    if (tid < HID) bsm[tid] = __ldg(bh + tid);

    const int q  = lane >> 3;
    const int ri = lane & 7;
    const int mchunk = wid & 7;
    const int nhalf  = wid >> 3;

    const uint32_t aLane = (uint32_t)(((mchunk * 16 + (q & 1) * 8 + ri) * UXSTR +
                                       (q >> 1) * 8) * 2);
    const uint32_t bLane = (uint32_t)(((nhalf * 112 + (q >> 1) * 8 + ri) * UWSTR +
                                       (q & 1) * 8) * 2);
    const uint32_t aHi = sbase + USM_XHI + aLane;
    const uint32_t aLo = sbase + USM_XLO + aLane;
    const uint32_t wHi = sbase + USM_WHI + bLane;
    const uint32_t wLo = sbase + USM_WLO + bLane;

    float acc[14][4];
    #pragma unroll
    for (int n = 0; n < 14; n++)
        #pragma unroll
        for (int i = 0; i < 4; i++) acc[n][i] = 0.f;

    for (int kc = 0; kc < 2; kc++) {
        const int kbase = kc * 112;
        __syncthreads();   // previous chunk mma done (and bsm written on kc=0)

        for (int i = tid; i < HID * 28; i += 512) {
            int r = i / 28, c4 = (i % 28) * 4;
            float4 v = __ldg((const float4*)(Wh + (size_t)r * HID + kbase + c4));
            uint2 hi, lo; split4(v, hi, lo);
            uint32_t off = (uint32_t)(r * UWSTR + c4) * 2u;
            *(uint2*)(smem + USM_WHI + off) = hi;
            *(uint2*)(smem + USM_WLO + off) = lo;
        }
        for (int i = tid; i < 128 * 28; i += 512) {
            int lr = i / 28, c4 = (i % 28) * 4;
            int row = r0g + lr;
            int kg = kbase + c4;
            float4 v = make_float4(0.f, 0.f, 0.f, 0.f);
            if (row < N_NODES) {
                if (kg < MSG) v = *(const float4*)(g_msum + (size_t)row * MSG + kg);
                else          v = *(const float4*)(h_n + (size_t)row * D_NODE + (kg - MSG));
            }
            uint2 hi, lo; split4(v, hi, lo);
            uint32_t off = (uint32_t)(lr * UXSTR + c4) * 2u;
            *(uint2*)(smem + USM_XHI + off) = hi;
            *(uint2*)(smem + USM_XLO + off) = lo;
        }
        __syncthreads();

        #pragma unroll 1
        for (int kk = 0; kk < 7; kk++) {
            const uint32_t kOff = (uint32_t)(kk * 32);
            uint32_t Ahi[4], Alo[4];
            ldsm_x4(Ahi, aHi + kOff);
            ldsm_x4(Alo, aLo + kOff);
            #pragma unroll
            for (int np = 0; np < 7; np++) {
                const uint32_t nOff = (uint32_t)(np * 16 * UWSTR * 2) + kOff;
                uint32_t Bhi[4], Blo[4];
                ldsm_x4(Bhi, wHi + nOff);
                ldsm_x4(Blo, wLo + nOff);
                mma_bf16(acc[np * 2],     Ahi, Bhi[0], Bhi[1]);
                mma_bf16(acc[np * 2],     Ahi, Blo[0], Blo[1]);
                mma_bf16(acc[np * 2],     Alo, Bhi[0], Bhi[1]);
                mma_bf16(acc[np * 2 + 1], Ahi, Bhi[2], Bhi[3]);
                mma_bf16(acc[np * 2 + 1], Ahi, Blo[2], Blo[3]);
                mma_bf16(acc[np * 2 + 1], Alo, Bhi[2], Bhi[3]);
            }
        }
    }

    // --- epilogue: bias + lrelu + direct STG.64 ---
    {
        const int rA = r0g + mchunk * 16 + (lane >> 2);
        const int rB = rA + 8;
        const int cb = nhalf * 112 + (lane & 3) * 2;
        #pragma unroll
        for (int n = 0; n < 14; n++) {
            int c = cb + n * 8;
            float b0 = bsm[c], b1 = bsm[c + 1];
            if (rA < N_NODES) {
                float2 v = make_float2(lrelu(acc[n][0] + b0), lrelu(acc[n][1] + b1));
                *(float2*)(out + (size_t)rA * HID + c) = v;
            }
            if (rB < N_NODES) {
                float2 v = make_float2(lrelu(acc[n][2] + b0), lrelu(acc[n][3] + b1));
                *(float2*)(out + (size_t)rB * HID + c) = v;
            }
        }
    }
}

// ---------------------------------------------------------------------------
extern "C" void kernel_launch(void* const* d_in, const int* in_sizes, int n_in,
                              void* d_out, int out_size)
{
    const float* h_n = (const float*)d_in[0];
    const float* h_e = (const float*)d_in[1];
    const int*   src = (const int*)d_in[2];
    const int*   dst = (const int*)d_in[3];
    const float* Wm  = (const float*)d_in[4];
    const float* bm  = (const float*)d_in[5];
    const float* Wh  = (const float*)d_in[6];
    const float* bh  = (const float*)d_in[7];
    float* out = (float*)d_out;

    cudaFuncSetAttribute(edge_kernel, cudaFuncAttributeMaxDynamicSharedMemorySize,
                         EDGE_SMEM_BYTES);
    cudaFuncSetAttribute(update_kernel, cudaFuncAttributeMaxDynamicSharedMemorySize,
                         UPD_SMEM_BYTES);

    zero_msum_kernel<<<2048, 256>>>();
    edge_kernel<<<152, 512, EDGE_SMEM_BYTES>>>(h_n, h_e, src, dst, Wm, bm);
    update_kernel<<<(N_NODES + 127) / 128, 512, UPD_SMEM_BYTES>>>(h_n, Wh, bh, out);
}

// round 10
// speedup vs baseline: 4.3280x; 1.1779x over previous
#include <cuda_runtime.h>
#include <cuda_fp16.h>
#include <cstdint>

#define N_NODES 50000
#define N_EDGES 500000
#define D_NODE  64
#define D_EDGE  32
#define MSG     160
#define HID     224
#define ALPHA   0.01f

#define NTILES  ((N_EDGES + 127) / 128)   // 3907

// 32 MB scratch for segment-sum accumulation
__device__ float g_msum[(size_t)N_NODES * MSG];

__device__ __forceinline__ float lrelu(float v) { return v > 0.f ? v : ALPHA * v; }

__device__ __forceinline__ uint32_t smem_u32(const void* p) {
    uint32_t a;
    asm("{ .reg .u64 t; cvta.to.shared.u64 t, %1; cvt.u32.u64 %0, t; }" : "=r"(a) : "l"(p));
    return a;
}

__device__ __forceinline__ void ldsm_x4(uint32_t* r, uint32_t addr) {
    asm volatile("ldmatrix.sync.aligned.m8n8.x4.shared.b16 {%0,%1,%2,%3}, [%4];"
                 : "=r"(r[0]), "=r"(r[1]), "=r"(r[2]), "=r"(r[3]) : "r"(addr));
}

__device__ __forceinline__ void mma_f16(float* d, const uint32_t* a,
                                        uint32_t b0, uint32_t b1) {
    asm volatile("mma.sync.aligned.m16n8k16.row.col.f32.f16.f16.f32 "
                 "{%0,%1,%2,%3}, {%4,%5,%6,%7}, {%8,%9}, {%0,%1,%2,%3};"
                 : "+f"(d[0]), "+f"(d[1]), "+f"(d[2]), "+f"(d[3])
                 : "r"(a[0]), "r"(a[1]), "r"(a[2]), "r"(a[3]), "r"(b0), "r"(b1));
}

// pack two floats into one f16x2 (lo = a, hi = b)
__device__ __forceinline__ uint32_t packh2(float a, float b) {
    uint32_t r;
    asm("cvt.rn.f16x2.f32 %0, %1, %2;" : "=r"(r) : "f"(b), "f"(a));
    return r;
}

// fp16 hi/lo split of a float4 (W prologue only)
__device__ __forceinline__ void splitW4(float4 v, uint2& hi, uint2& lo) {
    __half h0 = __float2half_rn(v.x), h1 = __float2half_rn(v.y);
    __half h2 = __float2half_rn(v.z), h3 = __float2half_rn(v.w);
    float l0 = v.x - __half2float(h0), l1 = v.y - __half2float(h1);
    float l2 = v.z - __half2float(h2), l3 = v.w - __half2float(h3);
    hi.x = ((uint32_t)__half_as_ushort(h1) << 16) | __half_as_ushort(h0);
    hi.y = ((uint32_t)__half_as_ushort(h3) << 16) | __half_as_ushort(h2);
    lo.x = packh2(l0, l1);
    lo.y = packh2(l2, l3);
}

// ---------------------------------------------------------------------------
// Kernel 0: zero the accumulator
// ---------------------------------------------------------------------------
__global__ void zero_msum_kernel() {
    size_t n4 = (size_t)N_NODES * MSG / 4;
    float4* p = (float4*)g_msum;
    for (size_t i = (size_t)blockIdx.x * blockDim.x + threadIdx.x; i < n4;
         i += (size_t)gridDim.x * blockDim.x)
        p[i] = make_float4(0.f, 0.f, 0.f, 0.f);
}

// ---------------------------------------------------------------------------
// Kernel 1: persistent edge kernel (mma.sync fp16 2-term: Xh*Wh + Xh*Wl)
//   Tile: 128 edges x 160 out, K=160. 512 threads,
//   16 warps = 8 m-chunks (16 edges) x 2 n-halves (80 outs)
// SMEM: X [128][168] f16 | WHI [160][168] f16 | WLO | bias f32 | dsm
// ---------------------------------------------------------------------------
#define XSTR  168
#define WSTR  168
#define SM_X     0
#define SM_WHI   43008
#define SM_WLO   96768
#define SM_BIAS  150528
#define SM_DSM   151168
#define EDGE_SMEM_BYTES 151680

__global__ __launch_bounds__(512, 1) void edge_kernel(
    const float* __restrict__ h_n, const float* __restrict__ h_e,
    const int* __restrict__ src, const int* __restrict__ dst,
    const float* __restrict__ Wm, const float* __restrict__ bm)
{
    extern __shared__ char smem[];
    const uint32_t sbase = smem_u32(smem);
    const int tid  = threadIdx.x;
    const int wid  = tid >> 5;
    const int lane = tid & 31;

    float* bsm = (float*)(smem + SM_BIAS);
    int*   dsm = (int*)(smem + SM_DSM);

    // --- prologue: convert W_msg to fp16 hi/lo into smem ---
    for (int i = tid; i < MSG * 40; i += 512) {
        int r = i / 40, c4 = (i % 40) * 4;
        float4 v = __ldg((const float4*)(Wm + r * MSG + c4));
        uint2 hi, lo; splitW4(v, hi, lo);
        uint32_t off = (uint32_t)(r * WSTR + c4) * 2u;
        *(uint2*)(smem + SM_WHI + off) = hi;
        *(uint2*)(smem + SM_WLO + off) = lo;
    }
    if (tid < MSG) bsm[tid] = __ldg(bm + tid);
    __syncthreads();

    const int q  = lane >> 3;
    const int ri = lane & 7;
    const int mchunk = wid & 7;       // 16-edge row group
    const int nhalf  = wid >> 3;      // 80-output column half
    // A quadrants: (r, k): q0=(+0,+0) q1=(+8,+0) q2=(+0,+8) q3=(+8,+8)
    const uint32_t aLane = (uint32_t)(((mchunk * 16 + (q & 1) * 8 + ri) * XSTR +
                                       (q >> 1) * 8) * 2);
    // B quadrants: (n, k): q0=(+0,+0) q1=(+0,+8) q2=(+8,+0) q3=(+8,+8)
    const uint32_t bLane = (uint32_t)(((nhalf * 80 + (q >> 1) * 8 + ri) * WSTR +
                                       (q & 1) * 8) * 2);

    const uint32_t aX  = sbase + SM_X + aLane;
    const uint32_t wHi = sbase + SM_WHI + bLane;
    const uint32_t wLo = sbase + SM_WLO + bLane;

    // gather mapping: 4 threads per edge, 10 float4 each
    const int gle = tid >> 2;          // edge slot 0..127
    const int gj0 = (tid & 3) * 10;    // first float4 index

    for (int tile = blockIdx.x; tile < NTILES; tile += gridDim.x) {
        const int e0 = tile * 128;
        __syncthreads();   // prev tile compute done; REDGs drain in background

        // --- gather + fp16 convert ---
        if (tid < 128) {
            int e = e0 + tid;
            dsm[tid] = (e < N_EDGES) ? __ldg(dst + e) : -1;
        }
        {
            const int e = e0 + gle;
            const bool valid = (e < N_EDGES);
            int s = 0, d = 0;
            if (valid) { s = __ldg(src + e); d = __ldg(dst + e); }
            const float4* ps = (const float4*)(h_n + (size_t)s * D_NODE);
            const float4* pd = (const float4*)(h_n + (size_t)d * D_NODE);
            const float4* pe = (const float4*)(h_e + (size_t)e * D_EDGE);
            #pragma unroll
            for (int i = 0; i < 10; i++) {
                const int j = gj0 + i;
                float4 v = make_float4(0.f, 0.f, 0.f, 0.f);
                if (valid) {
                    if (j < 16)      v = __ldg(ps + j);
                    else if (j < 32) v = __ldg(pd + (j - 16));
                    else             v = __ldg(pe + (j - 32));
                }
                uint2 hv;
                hv.x = packh2(v.x, v.y);
                hv.y = packh2(v.z, v.w);
                *(uint2*)(smem + SM_X + (uint32_t)(gle * XSTR + j * 4) * 2u) = hv;
            }
        }
        __syncthreads();   // X ready

        // --- compute: warp covers 16 edges x 80 outs: acc[10 n8][4] ---
        float acc[10][4];
        #pragma unroll
        for (int n = 0; n < 10; n++)
            #pragma unroll
            for (int i = 0; i < 4; i++) acc[n][i] = 0.f;

        #pragma unroll 2
        for (int kk = 0; kk < 10; kk++) {
            const uint32_t kOff = (uint32_t)(kk * 32);
            uint32_t A[4];
            ldsm_x4(A, aX + kOff);
            #pragma unroll
            for (int np = 0; np < 5; np++) {
                const uint32_t nOff = (uint32_t)(np * 16 * WSTR * 2) + kOff;
                uint32_t Bhi[4], Blo[4];
                ldsm_x4(Bhi, wHi + nOff);
                ldsm_x4(Blo, wLo + nOff);
                mma_f16(acc[np * 2],     A, Bhi[0], Bhi[1]);
                mma_f16(acc[np * 2],     A, Blo[0], Blo[1]);
                mma_f16(acc[np * 2 + 1], A, Bhi[2], Bhi[3]);
                mma_f16(acc[np * 2 + 1], A, Blo[2], Blo[3]);
            }
        }

        // --- epilogue: shfl pairs into v4, bias + lrelu + red.v4 scatter ---
        {
            const int g  = lane & 3;
            const int r0 = mchunk * 16 + (lane >> 2);
            const int d0 = dsm[r0];
            const int d1 = dsm[r0 + 8];
            const int cb = nhalf * 80;
            #pragma unroll
            for (int t = 0; t < 5; t++) {
                const int n0 = 2 * t, n1 = 2 * t + 1;
                #pragma unroll
                for (int h = 0; h < 2; h++) {
                    float ox0 = acc[n0][2 * h], ox1 = acc[n0][2 * h + 1];
                    float oy0 = acc[n1][2 * h], oy1 = acc[n1][2 * h + 1];
                    float s0 = (g & 1) ? ox0 : oy0;
                    float s1 = (g & 1) ? ox1 : oy1;
                    float rc0 = __shfl_xor_sync(0xffffffffu, s0, 1);
                    float rc1 = __shfl_xor_sync(0xffffffffu, s1, 1);
                    float v0, v1, v2, v3;
                    if (g & 1) { v0 = rc0; v1 = rc1; v2 = oy0; v3 = oy1; }
                    else       { v0 = ox0; v1 = ox1; v2 = rc0; v3 = rc1; }
                    const int c = cb + ((g & 1) ? n1 : n0) * 8 + (g & 2) * 2;
                    const int d = h ? d1 : d0;
                    if (d >= 0) {
                        float4 b = *(const float4*)(bsm + c);
                        v0 = lrelu(v0 + b.x); v1 = lrelu(v1 + b.y);
                        v2 = lrelu(v2 + b.z); v3 = lrelu(v3 + b.w);
                        asm volatile("red.global.add.v4.f32 [%0], {%1, %2, %3, %4};"
                                     :: "l"(g_msum + (size_t)d * MSG + c),
                                        "f"(v0), "f"(v1), "f"(v2), "f"(v3) : "memory");
                    }
                }
            }
        }
    }
}

// ---------------------------------------------------------------------------
// Kernel 2: update GEMM (fp16 2-term), 512 threads
//   Tile: 128 nodes x 224 out, K=224 in 2 chunks of 112.
// SMEM: X [128][120] f16 | WHI [224][120] f16 | WLO | bias f32
// ---------------------------------------------------------------------------
#define UXSTR 120
#define UWSTR 120
#define USM_X    0
#define USM_WHI  30720
#define USM_WLO  84480
#define USM_BIAS 138240
#define UPD_SMEM_BYTES 139136

__global__ __launch_bounds__(512, 1) void update_kernel(
    const float* __restrict__ h_n, const float* __restrict__ Wh,
    const float* __restrict__ bh, float* __restrict__ out)
{
    extern __shared__ char smem[];
    const uint32_t sbase = smem_u32(smem);
    const int tid  = threadIdx.x;
    const int wid  = tid >> 5;
    const int lane = tid & 31;
    const int r0g  = blockIdx.x * 128;

    float* bsm = (float*)(smem + USM_BIAS);
    if (tid < HID) bsm[tid] = __ldg(bh + tid);

    const int q  = lane >> 3;
    const int ri = lane & 7;
    const int mchunk = wid & 7;
    const int nhalf  = wid >> 3;

    const uint32_t aLane = (uint32_t)(((mchunk * 16 + (q & 1) * 8 + ri) * UXSTR +
                                       (q >> 1) * 8) * 2);
    const uint32_t bLane = (uint32_t)(((nhalf * 112 + (q >> 1) * 8 + ri) * UWSTR +
                                       (q & 1) * 8) * 2);
    const uint32_t aX  = sbase + USM_X + aLane;
    const uint32_t wHi = sbase + USM_WHI + bLane;
    const uint32_t wLo = sbase + USM_WLO + bLane;

    float acc[14][4];
    #pragma unroll
    for (int n = 0; n < 14; n++)
        #pragma unroll
        for (int i = 0; i < 4; i++) acc[n][i] = 0.f;

    for (int kc = 0; kc < 2; kc++) {
        const int kbase = kc * 112;
        __syncthreads();   // previous chunk mma done (and bsm written on kc=0)

        for (int i = tid; i < HID * 28; i += 512) {
            int r = i / 28, c4 = (i % 28) * 4;
            float4 v = __ldg((const float4*)(Wh + (size_t)r * HID + kbase + c4));
            uint2 hi, lo; splitW4(v, hi, lo);
            uint32_t off = (uint32_t)(r * UWSTR + c4) * 2u;
            *(uint2*)(smem + USM_WHI + off) = hi;
            *(uint2*)(smem + USM_WLO + off) = lo;
        }
        for (int i = tid; i < 128 * 28; i += 512) {
            int lr = i / 28, c4 = (i % 28) * 4;
            int row = r0g + lr;
            int kg = kbase + c4;
            float4 v = make_float4(0.f, 0.f, 0.f, 0.f);
            if (row < N_NODES) {
                if (kg < MSG) v = *(const float4*)(g_msum + (size_t)row * MSG + kg);
                else          v = *(const float4*)(h_n + (size_t)row * D_NODE + (kg - MSG));
            }
            uint2 hv;
            hv.x = packh2(v.x, v.y);
            hv.y = packh2(v.z, v.w);
            *(uint2*)(smem + USM_X + (uint32_t)(lr * UXSTR + c4) * 2u) = hv;
        }
        __syncthreads();

        #pragma unroll 1
        for (int kk = 0; kk < 7; kk++) {
            const uint32_t kOff = (uint32_t)(kk * 32);
            uint32_t A[4];
            ldsm_x4(A, aX + kOff);
            #pragma unroll
            for (int np = 0; np < 7; np++) {
                const uint32_t nOff = (uint32_t)(np * 16 * UWSTR * 2) + kOff;
                uint32_t Bhi[4], Blo[4];
                ldsm_x4(Bhi, wHi + nOff);
                ldsm_x4(Blo, wLo + nOff);
                mma_f16(acc[np * 2],     A, Bhi[0], Bhi[1]);
                mma_f16(acc[np * 2],     A, Blo[0], Blo[1]);
                mma_f16(acc[np * 2 + 1], A, Bhi[2], Bhi[3]);
                mma_f16(acc[np * 2 + 1], A, Blo[2], Blo[3]);
            }
        }
    }

    // --- epilogue: bias + lrelu + direct STG.64 ---
    {
        const int rA = r0g + mchunk * 16 + (lane >> 2);
        const int rB = rA + 8;
        const int cb = nhalf * 112 + (lane & 3) * 2;
        #pragma unroll
        for (int n = 0; n < 14; n++) {
            int c = cb + n * 8;
            float b0 = bsm[c], b1 = bsm[c + 1];
            if (rA < N_NODES) {
                float2 v = make_float2(lrelu(acc[n][0] + b0), lrelu(acc[n][1] + b1));
                *(float2*)(out + (size_t)rA * HID + c) = v;
            }
            if (rB < N_NODES) {
                float2 v = make_float2(lrelu(acc[n][2] + b0), lrelu(acc[n][3] + b1));
                *(float2*)(out + (size_t)rB * HID + c) = v;
            }
        }
    }
}

// ---------------------------------------------------------------------------
extern "C" void kernel_launch(void* const* d_in, const int* in_sizes, int n_in,
                              void* d_out, int out_size)
{
    const float* h_n = (const float*)d_in[0];
    const float* h_e = (const float*)d_in[1];
    const int*   src = (const int*)d_in[2];
    const int*   dst = (const int*)d_in[3];
    const float* Wm  = (const float*)d_in[4];
    const float* bm  = (const float*)d_in[5];
    const float* Wh  = (const float*)d_in[6];
    const float* bh  = (const float*)d_in[7];
    float* out = (float*)d_out;

    cudaFuncSetAttribute(edge_kernel, cudaFuncAttributeMaxDynamicSharedMemorySize,
                         EDGE_SMEM_BYTES);
    cudaFuncSetAttribute(update_kernel, cudaFuncAttributeMaxDynamicSharedMemorySize,
                         UPD_SMEM_BYTES);

    zero_msum_kernel<<<2048, 256>>>();
    edge_kernel<<<152, 512, EDGE_SMEM_BYTES>>>(h_n, h_e, src, dst, Wm, bm);
    update_kernel<<<(N_NODES + 127) / 128, 512, UPD_SMEM_BYTES>>>(h_n, Wh, bh, out);
}

// round 11
// speedup vs baseline: 4.5631x; 1.0543x over previous
#include <cuda_runtime.h>
#include <cuda_fp16.h>
#include <cstdint>

#define N_NODES 50000
#define N_EDGES 500000
#define D_NODE  64
#define D_EDGE  32
#define MSG     160
#define HID     224
#define ALPHA   0.01f

#define NTILES_E ((N_EDGES + 255) / 256)   // 1954

// 32 MB scratch for segment-sum accumulation
__device__ float g_msum[(size_t)N_NODES * MSG];

__device__ __forceinline__ float lrelu(float v) { return v > 0.f ? v : ALPHA * v; }

__device__ __forceinline__ uint32_t smem_u32(const void* p) {
    uint32_t a;
    asm("{ .reg .u64 t; cvta.to.shared.u64 t, %1; cvt.u32.u64 %0, t; }" : "=r"(a) : "l"(p));
    return a;
}

__device__ __forceinline__ void ldsm_x4(uint32_t* r, uint32_t addr) {
    asm volatile("ldmatrix.sync.aligned.m8n8.x4.shared.b16 {%0,%1,%2,%3}, [%4];"
                 : "=r"(r[0]), "=r"(r[1]), "=r"(r[2]), "=r"(r[3]) : "r"(addr));
}

__device__ __forceinline__ void mma_f16(float* d, const uint32_t* a,
                                        uint32_t b0, uint32_t b1) {
    asm volatile("mma.sync.aligned.m16n8k16.row.col.f32.f16.f16.f32 "
                 "{%0,%1,%2,%3}, {%4,%5,%6,%7}, {%8,%9}, {%0,%1,%2,%3};"
                 : "+f"(d[0]), "+f"(d[1]), "+f"(d[2]), "+f"(d[3])
                 : "r"(a[0]), "r"(a[1]), "r"(a[2]), "r"(a[3]), "r"(b0), "r"(b1));
}

// pack two floats into one f16x2 (lo = a, hi = b)
__device__ __forceinline__ uint32_t packh2(float a, float b) {
    uint32_t r;
    asm("cvt.rn.f16x2.f32 %0, %1, %2;" : "=r"(r) : "f"(b), "f"(a));
    return r;
}

// fp16 hi/lo split of a float4 (W prologue only)
__device__ __forceinline__ void splitW4(float4 v, uint2& hi, uint2& lo) {
    __half h0 = __float2half_rn(v.x), h1 = __float2half_rn(v.y);
    __half h2 = __float2half_rn(v.z), h3 = __float2half_rn(v.w);
    float l0 = v.x - __half2float(h0), l1 = v.y - __half2float(h1);
    float l2 = v.z - __half2float(h2), l3 = v.w - __half2float(h3);
    hi.x = ((uint32_t)__half_as_ushort(h1) << 16) | __half_as_ushort(h0);
    hi.y = ((uint32_t)__half_as_ushort(h3) << 16) | __half_as_ushort(h2);
    lo.x = packh2(l0, l1);
    lo.y = packh2(l2, l3);
}

// ---------------------------------------------------------------------------
// Kernel 0: zero the accumulator
// ---------------------------------------------------------------------------
__global__ void zero_msum_kernel() {
    size_t n4 = (size_t)N_NODES * MSG / 4;
    float4* p = (float4*)g_msum;
    for (size_t i = (size_t)blockIdx.x * blockDim.x + threadIdx.x; i < n4;
         i += (size_t)gridDim.x * blockDim.x)
        p[i] = make_float4(0.f, 0.f, 0.f, 0.f);
}

// ---------------------------------------------------------------------------
// Kernel 1: persistent edge kernel (mma.sync fp16 2-term: Xh*Wh + Xh*Wl)
//   Tile: 256 edges x 160 out, K=160. 512 threads.
//   16 warps = 8 m-chunks (32 edges) x 2 n-halves (80 outs)
// SMEM: X [256][168] f16 | WHI [160][168] f16 | WLO | bias f32 | dsm[256]
// ---------------------------------------------------------------------------
#define XSTR  168
#define WSTR  168
#define SM_X     0
#define SM_WHI   86016
#define SM_WLO   139776
#define SM_BIAS  193536
#define SM_DSM   194176
#define EDGE_SMEM_BYTES 195200
#define MH_OFF (16 * XSTR * 2)   // byte offset between the two 16-edge m-halves

__global__ __launch_bounds__(512, 1) void edge_kernel(
    const float* __restrict__ h_n, const float* __restrict__ h_e,
    const int* __restrict__ src, const int* __restrict__ dst,
    const float* __restrict__ Wm, const float* __restrict__ bm)
{
    extern __shared__ char smem[];
    const uint32_t sbase = smem_u32(smem);
    const int tid  = threadIdx.x;
    const int wid  = tid >> 5;
    const int lane = tid & 31;

    float* bsm = (float*)(smem + SM_BIAS);
    int*   dsm = (int*)(smem + SM_DSM);

    // --- prologue: convert W_msg to fp16 hi/lo into smem ---
    for (int i = tid; i < MSG * 40; i += 512) {
        int r = i / 40, c4 = (i % 40) * 4;
        float4 v = __ldg((const float4*)(Wm + r * MSG + c4));
        uint2 hi, lo; splitW4(v, hi, lo);
        uint32_t off = (uint32_t)(r * WSTR + c4) * 2u;
        *(uint2*)(smem + SM_WHI + off) = hi;
        *(uint2*)(smem + SM_WLO + off) = lo;
    }
    if (tid < MSG) bsm[tid] = __ldg(bm + tid);
    __syncthreads();

    const int q  = lane >> 3;
    const int ri = lane & 7;
    const int mchunk = wid & 7;       // 32-edge row group
    const int nhalf  = wid >> 3;      // 80-output column half
    // A quadrants: (r, k): q0=(+0,+0) q1=(+8,+0) q2=(+0,+8) q3=(+8,+8)
    const uint32_t aLane = (uint32_t)(((mchunk * 32 + (q & 1) * 8 + ri) * XSTR +
                                       (q >> 1) * 8) * 2);
    // B quadrants: (n, k): q0=(+0,+0) q1=(+0,+8) q2=(+8,+0) q3=(+8,+8)
    const uint32_t bLane = (uint32_t)(((nhalf * 80 + (q >> 1) * 8 + ri) * WSTR +
                                       (q & 1) * 8) * 2);

    const uint32_t aX  = sbase + SM_X + aLane;
    const uint32_t wHi = sbase + SM_WHI + bLane;
    const uint32_t wLo = sbase + SM_WLO + bLane;

    // gather mapping: 2 threads per edge, 20 float4 each
    const int gle = tid >> 1;          // edge slot 0..255
    const int gj0 = (tid & 1) * 20;    // first float4 index

    for (int tile = blockIdx.x; tile < NTILES_E; tile += gridDim.x) {
        const int e0 = tile * 256;
        __syncthreads();   // prev tile compute done; REDGs drain in background

        // --- gather + fp16 convert ---
        if (tid < 256) {
            int e = e0 + tid;
            dsm[tid] = (e < N_EDGES) ? __ldg(dst + e) : -1;
        }
        {
            const int e = e0 + gle;
            const bool valid = (e < N_EDGES);
            int s = 0, d = 0;
            if (valid) { s = __ldg(src + e); d = __ldg(dst + e); }
            const float4* ps = (const float4*)(h_n + (size_t)s * D_NODE);
            const float4* pd = (const float4*)(h_n + (size_t)d * D_NODE);
            const float4* pe = (const float4*)(h_e + (size_t)e * D_EDGE);
            #pragma unroll
            for (int i = 0; i < 20; i++) {
                const int j = gj0 + i;
                float4 v = make_float4(0.f, 0.f, 0.f, 0.f);
                if (valid) {
                    if (j < 16)      v = __ldg(ps + j);
                    else if (j < 32) v = __ldg(pd + (j - 16));
                    else             v = __ldg(pe + (j - 32));
                }
                uint2 hv;
                hv.x = packh2(v.x, v.y);
                hv.y = packh2(v.z, v.w);
                *(uint2*)(smem + SM_X + (uint32_t)(gle * XSTR + j * 4) * 2u) = hv;
            }
        }
        __syncthreads();   // X ready

        // --- compute: warp covers 32 edges x 80 outs: acc[2 mh][10 n8][4] ---
        float acc[2][10][4];
        #pragma unroll
        for (int mh = 0; mh < 2; mh++)
            #pragma unroll
            for (int n = 0; n < 10; n++)
                #pragma unroll
                for (int i = 0; i < 4; i++) acc[mh][n][i] = 0.f;

        #pragma unroll 1
        for (int kk = 0; kk < 10; kk++) {
            const uint32_t kOff = (uint32_t)(kk * 32);
            uint32_t A0[4], A1[4];
            ldsm_x4(A0, aX + kOff);
            ldsm_x4(A1, aX + MH_OFF + kOff);
            #pragma unroll
            for (int np = 0; np < 5; np++) {
                const uint32_t nOff = (uint32_t)(np * 16 * WSTR * 2) + kOff;
                uint32_t Bhi[4], Blo[4];
                ldsm_x4(Bhi, wHi + nOff);
                ldsm_x4(Blo, wLo + nOff);
                mma_f16(acc[0][np * 2],     A0, Bhi[0], Bhi[1]);
                mma_f16(acc[0][np * 2],     A0, Blo[0], Blo[1]);
                mma_f16(acc[1][np * 2],     A1, Bhi[0], Bhi[1]);
                mma_f16(acc[1][np * 2],     A1, Blo[0], Blo[1]);
                mma_f16(acc[0][np * 2 + 1], A0, Bhi[2], Bhi[3]);
                mma_f16(acc[0][np * 2 + 1], A0, Blo[2], Blo[3]);
                mma_f16(acc[1][np * 2 + 1], A1, Bhi[2], Bhi[3]);
                mma_f16(acc[1][np * 2 + 1], A1, Blo[2], Blo[3]);
            }
        }

        // --- epilogue: shfl pairs into v4, bias + lrelu + red.v4 scatter ---
        {
            const int g  = lane & 3;
            const int cb = nhalf * 80;
            #pragma unroll
            for (int mh = 0; mh < 2; mh++) {
                const int r0 = mchunk * 32 + mh * 16 + (lane >> 2);
                const int d0 = dsm[r0];
                const int d1 = dsm[r0 + 8];
                #pragma unroll
                for (int t = 0; t < 5; t++) {
                    const int n0 = 2 * t, n1 = 2 * t + 1;
                    #pragma unroll
                    for (int h = 0; h < 2; h++) {
                        float ox0 = acc[mh][n0][2 * h], ox1 = acc[mh][n0][2 * h + 1];
                        float oy0 = acc[mh][n1][2 * h], oy1 = acc[mh][n1][2 * h + 1];
                        float s0 = (g & 1) ? ox0 : oy0;
                        float s1 = (g & 1) ? ox1 : oy1;
                        float rc0 = __shfl_xor_sync(0xffffffffu, s0, 1);
                        float rc1 = __shfl_xor_sync(0xffffffffu, s1, 1);
                        float v0, v1, v2, v3;
                        if (g & 1) { v0 = rc0; v1 = rc1; v2 = oy0; v3 = oy1; }
                        else       { v0 = ox0; v1 = ox1; v2 = rc0; v3 = rc1; }
                        const int c = cb + ((g & 1) ? n1 : n0) * 8 + (g & 2) * 2;
                        const int d = h ? d1 : d0;
                        if (d >= 0) {
                            float4 b = *(const float4*)(bsm + c);
                            v0 = lrelu(v0 + b.x); v1 = lrelu(v1 + b.y);
                            v2 = lrelu(v2 + b.z); v3 = lrelu(v3 + b.w);
                            asm volatile("red.global.add.v4.f32 [%0], {%1, %2, %3, %4};"
                                         :: "l"(g_msum + (size_t)d * MSG + c),
                                            "f"(v0), "f"(v1), "f"(v2), "f"(v3) : "memory");
                        }
                    }
                }
            }
        }
    }
}

// ---------------------------------------------------------------------------
// Kernel 2: update GEMM (fp16 2-term), 512 threads (validated R10)
//   Tile: 128 nodes x 224 out, K=224 in 2 chunks of 112.
// ---------------------------------------------------------------------------
#define UXSTR 120
#define UWSTR 120
#define USM_X    0
#define USM_WHI  30720
#define USM_WLO  84480
#define USM_BIAS 138240
#define UPD_SMEM_BYTES 139136

__global__ __launch_bounds__(512, 1) void update_kernel(
    const float* __restrict__ h_n, const float* __restrict__ Wh,
    const float* __restrict__ bh, float* __restrict__ out)
{
    extern __shared__ char smem[];
    const uint32_t sbase = smem_u32(smem);
    const int tid  = threadIdx.x;
    const int wid  = tid >> 5;
    const int lane = tid & 31;
    const int r0g  = blockIdx.x * 128;

    float* bsm = (float*)(smem + USM_BIAS);
    if (tid < HID) bsm[tid] = __ldg(bh + tid);

    const int q  = lane >> 3;
    const int ri = lane & 7;
    const int mchunk = wid & 7;
    const int nhalf  = wid >> 3;

    const uint32_t aLane = (uint32_t)(((mchunk * 16 + (q & 1) * 8 + ri) * UXSTR +
                                       (q >> 1) * 8) * 2);
    const uint32_t bLane = (uint32_t)(((nhalf * 112 + (q >> 1) * 8 + ri) * UWSTR +
                                       (q & 1) * 8) * 2);
    const uint32_t aX  = sbase + USM_X + aLane;
    const uint32_t wHi = sbase + USM_WHI + bLane;
    const uint32_t wLo = sbase + USM_WLO + bLane;

    float acc[14][4];
    #pragma unroll
    for (int n = 0; n < 14; n++)
        #pragma unroll
        for (int i = 0; i < 4; i++) acc[n][i] = 0.f;

    for (int kc = 0; kc < 2; kc++) {
        const int kbase = kc * 112;
        __syncthreads();   // previous chunk mma done (and bsm written on kc=0)

        for (int i = tid; i < HID * 28; i += 512) {
            int r = i / 28, c4 = (i % 28) * 4;
            float4 v = __ldg((const float4*)(Wh + (size_t)r * HID + kbase + c4));
            uint2 hi, lo; splitW4(v, hi, lo);
            uint32_t off = (uint32_t)(r * UWSTR + c4) * 2u;
            *(uint2*)(smem + USM_WHI + off) = hi;
            *(uint2*)(smem + USM_WLO + off) = lo;
        }
        for (int i = tid; i < 128 * 28; i += 512) {
            int lr = i / 28, c4 = (i % 28) * 4;
            int row = r0g + lr;
            int kg = kbase + c4;
            float4 v = make_float4(0.f, 0.f, 0.f, 0.f);
            if (row < N_NODES) {
                if (kg < MSG) v = *(const float4*)(g_msum + (size_t)row * MSG + kg);
                else          v = *(const float4*)(h_n + (size_t)row * D_NODE + (kg - MSG));
            }
            uint2 hv;
            hv.x = packh2(v.x, v.y);
            hv.y = packh2(v.z, v.w);
            *(uint2*)(smem + USM_X + (uint32_t)(lr * UXSTR + c4) * 2u) = hv;
        }
        __syncthreads();

        #pragma unroll 1
        for (int kk = 0; kk < 7; kk++) {
            const uint32_t kOff = (uint32_t)(kk * 32);
            uint32_t A[4];
            ldsm_x4(A, aX + kOff);
            #pragma unroll
            for (int np = 0; np < 7; np++) {
                const uint32_t nOff = (uint32_t)(np * 16 * UWSTR * 2) + kOff;
                uint32_t Bhi[4], Blo[4];
                ldsm_x4(Bhi, wHi + nOff);
                ldsm_x4(Blo, wLo + nOff);
                mma_f16(acc[np * 2],     A, Bhi[0], Bhi[1]);
                mma_f16(acc[np * 2],     A, Blo[0], Blo[1]);
                mma_f16(acc[np * 2 + 1], A, Bhi[2], Bhi[3]);
                mma_f16(acc[np * 2 + 1], A, Blo[2], Blo[3]);
            }
        }
    }

    // --- epilogue: bias + lrelu + direct STG.64 ---
    {
        const int rA = r0g + mchunk * 16 + (lane >> 2);
        const int rB = rA + 8;
        const int cb = nhalf * 112 + (lane & 3) * 2;
        #pragma unroll
        for (int n = 0; n < 14; n++) {
            int c = cb + n * 8;
            float b0 = bsm[c], b1 = bsm[c + 1];
            if (rA < N_NODES) {
                float2 v = make_float2(lrelu(acc[n][0] + b0), lrelu(acc[n][1] + b1));
                *(float2*)(out + (size_t)rA * HID + c) = v;
            }
            if (rB < N_NODES) {
                float2 v = make_float2(lrelu(acc[n][2] + b0), lrelu(acc[n][3] + b1));
                *(float2*)(out + (size_t)rB * HID + c) = v;
            }
        }
    }
}

// ---------------------------------------------------------------------------
extern "C" void kernel_launch(void* const* d_in, const int* in_sizes, int n_in,
                              void* d_out, int out_size)
{
    const float* h_n = (const float*)d_in[0];
    const float* h_e = (const float*)d_in[1];
    const int*   src = (const int*)d_in[2];
    const int*   dst = (const int*)d_in[3];
    const float* Wm  = (const float*)d_in[4];
    const float* bm  = (const float*)d_in[5];
    const float* Wh  = (const float*)d_in[6];
    const float* bh  = (const float*)d_in[7];
    float* out = (float*)d_out;

    cudaFuncSetAttribute(edge_kernel, cudaFuncAttributeMaxDynamicSharedMemorySize,
                         EDGE_SMEM_BYTES);
    cudaFuncSetAttribute(update_kernel, cudaFuncAttributeMaxDynamicSharedMemorySize,
                         UPD_SMEM_BYTES);

    zero_msum_kernel<<<2048, 256>>>();
    edge_kernel<<<152, 512, EDGE_SMEM_BYTES>>>(h_n, h_e, src, dst, Wm, bm);
    update_kernel<<<(N_NODES + 127) / 128, 512, UPD_SMEM_BYTES>>>(h_n, Wh, bh, out);
}

// round 13
// speedup vs baseline: 4.7039x; 1.0309x over previous
#include <cuda_runtime.h>
#include <cuda_fp16.h>
#include <cstdint>

#define N_NODES 50000
#define N_EDGES 500000
#define D_NODE  64
#define D_EDGE  32
#define MSG     160
#define HID     224
#define ALPHA   0.01f

#define NTILES  ((N_EDGES + 127) / 128)   // 3907

// 32 MB scratch for segment-sum accumulation
__device__ float g_msum[(size_t)N_NODES * MSG];

__device__ __forceinline__ float lrelu(float v) { return v > 0.f ? v : ALPHA * v; }

__device__ __forceinline__ uint32_t smem_u32(const void* p) {
    uint32_t a;
    asm("{ .reg .u64 t; cvta.to.shared.u64 t, %1; cvt.u32.u64 %0, t; }" : "=r"(a) : "l"(p));
    return a;
}

__device__ __forceinline__ void ldsm_x4(uint32_t* r, uint32_t addr) {
    asm volatile("ldmatrix.sync.aligned.m8n8.x4.shared.b16 {%0,%1,%2,%3}, [%4];"
                 : "=r"(r[0]), "=r"(r[1]), "=r"(r[2]), "=r"(r[3]) : "r"(addr));
}

__device__ __forceinline__ void mma_f16(float* d, const uint32_t* a,
                                        uint32_t b0, uint32_t b1) {
    asm volatile("mma.sync.aligned.m16n8k16.row.col.f32.f16.f16.f32 "
                 "{%0,%1,%2,%3}, {%4,%5,%6,%7}, {%8,%9}, {%0,%1,%2,%3};"
                 : "+f"(d[0]), "+f"(d[1]), "+f"(d[2]), "+f"(d[3])
                 : "r"(a[0]), "r"(a[1]), "r"(a[2]), "r"(a[3]), "r"(b0), "r"(b1));
}

// pack two floats into one f16x2 (lo = a, hi = b)
__device__ __forceinline__ uint32_t packh2(float a, float b) {
    uint32_t r;
    asm("cvt.rn.f16x2.f32 %0, %1, %2;" : "=r"(r) : "f"(b), "f"(a));
    return r;
}

// fp16 hi/lo split of a float4 (W prologue only)
__device__ __forceinline__ void splitW4(float4 v, uint2& hi, uint2& lo) {
    __half h0 = __float2half_rn(v.x), h1 = __float2half_rn(v.y);
    __half h2 = __float2half_rn(v.z), h3 = __float2half_rn(v.w);
    float l0 = v.x - __half2float(h0), l1 = v.y - __half2float(h1);
    float l2 = v.z - __half2float(h2), l3 = v.w - __half2float(h3);
    hi.x = ((uint32_t)__half_as_ushort(h1) << 16) | __half_as_ushort(h0);
    hi.y = ((uint32_t)__half_as_ushort(h3) << 16) | __half_as_ushort(h2);
    lo.x = packh2(l0, l1);
    lo.y = packh2(l2, l3);
}

// ---------------------------------------------------------------------------
// Kernel 0: zero the accumulator
// ---------------------------------------------------------------------------
__global__ void zero_msum_kernel() {
    size_t n4 = (size_t)N_NODES * MSG / 4;
    float4* p = (float4*)g_msum;
    for (size_t i = (size_t)blockIdx.x * blockDim.x + threadIdx.x; i < n4;
         i += (size_t)gridDim.x * blockDim.x)
        p[i] = make_float4(0.f, 0.f, 0.f, 0.f);
}

// ---------------------------------------------------------------------------
// Kernel 1: persistent edge kernel (fp16 2-term), register-pipelined gather
//   Tile: 128 edges x 160 out, K=160. 512 threads.
//   16 warps = 8 m-chunks (16 edges) x 2 n-halves (80 outs)
//   Gather for tile t+1 issued into regs before tile t's MMA (latency hidden).
// SMEM: X [128][168] f16 | WHI [160][168] f16 | WLO | bias f32 | dsm[128]
// ---------------------------------------------------------------------------
#define XSTR  168
#define WSTR  168
#define SM_X     0
#define SM_WHI   43008
#define SM_WLO   96768
#define SM_BIAS  150528
#define SM_DSM   151168
#define EDGE_SMEM_BYTES 151680

__global__ __launch_bounds__(512, 1) void edge_kernel(
    const float* __restrict__ h_n, const float* __restrict__ h_e,
    const int* __restrict__ src, const int* __restrict__ dst,
    const float* __restrict__ Wm, const float* __restrict__ bm)
{
    extern __shared__ char smem[];
    const uint32_t sbase = smem_u32(smem);
    const int tid  = threadIdx.x;
    const int wid  = tid >> 5;
    const int lane = tid & 31;

    float* bsm = (float*)(smem + SM_BIAS);
    int*   dsm = (int*)(smem + SM_DSM);

    // --- prologue: convert W_msg to fp16 hi/lo into smem ---
    for (int i = tid; i < MSG * 40; i += 512) {
        int r = i / 40, c4 = (i % 40) * 4;
        float4 v = __ldg((const float4*)(Wm + r * MSG + c4));
        uint2 hi, lo; splitW4(v, hi, lo);
        uint32_t off = (uint32_t)(r * WSTR + c4) * 2u;
        *(uint2*)(smem + SM_WHI + off) = hi;
        *(uint2*)(smem + SM_WLO + off) = lo;
    }
    if (tid < MSG) bsm[tid] = __ldg(bm + tid);

    const int q  = lane >> 3;
    const int ri = lane & 7;
    const int mchunk = wid & 7;       // 16-edge row group
    const int nhalf  = wid >> 3;      // 80-output column half
    const uint32_t aLane = (uint32_t)(((mchunk * 16 + (q & 1) * 8 + ri) * XSTR +
                                       (q >> 1) * 8) * 2);
    const uint32_t bLane = (uint32_t)(((nhalf * 80 + (q >> 1) * 8 + ri) * WSTR +
                                       (q & 1) * 8) * 2);
    const uint32_t aX  = sbase + SM_X + aLane;
    const uint32_t wHi = sbase + SM_WHI + bLane;
    const uint32_t wLo = sbase + SM_WLO + bLane;

    // gather mapping: 4 threads per edge, 10 float4 each
    const int gle = tid >> 2;          // edge slot 0..127
    const int gj0 = (tid & 3) * 10;    // first float4 index

    // held gather state for the NEXT tile to be stored
    float4 G[10];
    int    Gd = -1;                    // dst of this thread's edge

    auto do_gather = [&](int tt) {
        const int e = tt * 128 + gle;
        const bool valid = (tt < NTILES) && (e < N_EDGES);
        int s = 0, d = 0;
        if (valid) { s = __ldg(src + e); d = __ldg(dst + e); }
        Gd = valid ? d : -1;
        const float4* ps = (const float4*)(h_n + (size_t)s * D_NODE);
        const float4* pd = (const float4*)(h_n + (size_t)d * D_NODE);
        const float4* pe = (const float4*)(h_e + (size_t)e * D_EDGE);
        #pragma unroll
        for (int i = 0; i < 10; i++) {
            const int j = gj0 + i;
            float4 v = make_float4(0.f, 0.f, 0.f, 0.f);
            if (valid) {
                if (j < 16)      v = __ldg(ps + j);
                else if (j < 32) v = __ldg(pd + (j - 16));
                else             v = __ldg(pe + (j - 32));
            }
            G[i] = v;
        }
    };

    // prologue gather: first tile for this CTA
    do_gather(blockIdx.x);
    __syncthreads();   // W/bias ready (overlaps with prologue gather latency)

    for (int tile = blockIdx.x; tile < NTILES; tile += gridDim.x) {
        // --- store held tile into smem (convert fp32->fp16 now) ---
        if ((tid & 3) == 0) dsm[gle] = Gd;
        #pragma unroll
        for (int i = 0; i < 10; i++) {
            const int j = gj0 + i;
            uint2 hv;
            hv.x = packh2(G[i].x, G[i].y);
            hv.y = packh2(G[i].z, G[i].w);
            *(uint2*)(smem + SM_X + (uint32_t)(gle * XSTR + j * 4) * 2u) = hv;
        }
        __syncthreads();   // X + dsm ready

        // --- issue gather for the next tile (latency hidden by MMA below) ---
        do_gather(tile + gridDim.x);

        // --- compute: warp covers 16 edges x 80 outs: acc[10 n8][4] ---
        float acc[10][4];
        #pragma unroll
        for (int n = 0; n < 10; n++)
            #pragma unroll
            for (int i = 0; i < 4; i++) acc[n][i] = 0.f;

        #pragma unroll 1
        for (int kk = 0; kk < 10; kk++) {
            const uint32_t kOff = (uint32_t)(kk * 32);
            uint32_t A[4];
            ldsm_x4(A, aX + kOff);
            #pragma unroll
            for (int np = 0; np < 5; np++) {
                const uint32_t nOff = (uint32_t)(np * 16 * WSTR * 2) + kOff;
                uint32_t Bhi[4], Blo[4];
                ldsm_x4(Bhi, wHi + nOff);
                ldsm_x4(Blo, wLo + nOff);
                mma_f16(acc[np * 2],     A, Bhi[0], Bhi[1]);
                mma_f16(acc[np * 2],     A, Blo[0], Blo[1]);
                mma_f16(acc[np * 2 + 1], A, Bhi[2], Bhi[3]);
                mma_f16(acc[np * 2 + 1], A, Blo[2], Blo[3]);
            }
        }

        // --- epilogue: shfl pairs into v4, bias + lrelu + red.v4 scatter ---
        {
            const int g  = lane & 3;
            const int r0 = mchunk * 16 + (lane >> 2);
            const int d0 = dsm[r0];
            const int d1 = dsm[r0 + 8];
            const int cb = nhalf * 80;
            #pragma unroll
            for (int t = 0; t < 5; t++) {
                const int n0 = 2 * t, n1 = 2 * t + 1;
                #pragma unroll
                for (int h = 0; h < 2; h++) {
                    float ox0 = acc[n0][2 * h], ox1 = acc[n0][2 * h + 1];
                    float oy0 = acc[n1][2 * h], oy1 = acc[n1][2 * h + 1];
                    float s0 = (g & 1) ? ox0 : oy0;
                    float s1 = (g & 1) ? ox1 : oy1;
                    float rc0 = __shfl_xor_sync(0xffffffffu, s0, 1);
                    float rc1 = __shfl_xor_sync(0xffffffffu, s1, 1);
                    float v0, v1, v2, v3;
                    if (g & 1) { v0 = rc0; v1 = rc1; v2 = oy0; v3 = oy1; }
                    else       { v0 = ox0; v1 = ox1; v2 = rc0; v3 = rc1; }
                    const int c = cb + ((g & 1) ? n1 : n0) * 8 + (g & 2) * 2;
                    const int d = h ? d1 : d0;
                    if (d >= 0) {
                        float4 b = *(const float4*)(bsm + c);
                        v0 = lrelu(v0 + b.x); v1 = lrelu(v1 + b.y);
                        v2 = lrelu(v2 + b.z); v3 = lrelu(v3 + b.w);
                        asm volatile("red.global.add.v4.f32 [%0], {%1, %2, %3, %4};"
                                     :: "l"(g_msum + (size_t)d * MSG + c),
                                        "f"(v0), "f"(v1), "f"(v2), "f"(v3) : "memory");
                    }
                }
            }
        }
        __syncthreads();   // all reads of X/dsm done before next store phase
    }
}

// ---------------------------------------------------------------------------
// Kernel 2: update GEMM (fp16 2-term), 512 threads (validated R10)
//   Tile: 128 nodes x 224 out, K=224 in 2 chunks of 112.
// ---------------------------------------------------------------------------
#define UXSTR 120
#define UWSTR 120
#define USM_X    0
#define USM_WHI  30720
#define USM_WLO  84480
#define USM_BIAS 138240
#define UPD_SMEM_BYTES 139136

__global__ __launch_bounds__(512, 1) void update_kernel(
    const float* __restrict__ h_n, const float* __restrict__ Wh,
    const float* __restrict__ bh, float* __restrict__ out)
{
    extern __shared__ char smem[];
    const uint32_t sbase = smem_u32(smem);
    const int tid  = threadIdx.x;
    const int wid  = tid >> 5;
    const int lane = tid & 31;
    const int r0g  = blockIdx.x * 128;

    float* bsm = (float*)(smem + USM_BIAS);
    if (tid < HID) bsm[tid] = __ldg(bh + tid);

    const int q  = lane >> 3;
    const int ri = lane & 7;
    const int mchunk = wid & 7;
    const int nhalf  = wid >> 3;

    const uint32_t aLane = (uint32_t)(((mchunk * 16 + (q & 1) * 8 + ri) * UXSTR +
                                       (q >> 1) * 8) * 2);
    const uint32_t bLane = (uint32_t)(((nhalf * 112 + (q >> 1) * 8 + ri) * UWSTR +
                                       (q & 1) * 8) * 2);
    const uint32_t aX  = sbase + USM_X + aLane;
    const uint32_t wHi = sbase + USM_WHI + bLane;
    const uint32_t wLo = sbase + USM_WLO + bLane;

    float acc[14][4];
    #pragma unroll
    for (int n = 0; n < 14; n++)
        #pragma unroll
        for (int i = 0; i < 4; i++) acc[n][i] = 0.f;

    for (int kc = 0; kc < 2; kc++) {
        const int kbase = kc * 112;
        __syncthreads();   // previous chunk mma done (and bsm written on kc=0)

        for (int i = tid; i < HID * 28; i += 512) {
            int r = i / 28, c4 = (i % 28) * 4;
            float4 v = __ldg((const float4*)(Wh + (size_t)r * HID + kbase + c4));
            uint2 hi, lo; splitW4(v, hi, lo);
            uint32_t off = (uint32_t)(r * UWSTR + c4) * 2u;
            *(uint2*)(smem + USM_WHI + off) = hi;
            *(uint2*)(smem + USM_WLO + off) = lo;
        }
        for (int i = tid; i < 128 * 28; i += 512) {
            int lr = i / 28, c4 = (i % 28) * 4;
            int row = r0g + lr;
            int kg = kbase + c4;
            float4 v = make_float4(0.f, 0.f, 0.f, 0.f);
            if (row < N_NODES) {
                if (kg < MSG) v = *(const float4*)(g_msum + (size_t)row * MSG + kg);
                else          v = *(const float4*)(h_n + (size_t)row * D_NODE + (kg - MSG));
            }
            uint2 hv;
            hv.x = packh2(v.x, v.y);
            hv.y = packh2(v.z, v.w);
            *(uint2*)(smem + USM_X + (uint32_t)(lr * UXSTR + c4) * 2u) = hv;
        }
        __syncthreads();

        #pragma unroll 1
        for (int kk = 0; kk < 7; kk++) {
            const uint32_t kOff = (uint32_t)(kk * 32);
            uint32_t A[4];
            ldsm_x4(A, aX + kOff);
            #pragma unroll
            for (int np = 0; np < 7; np++) {
                const uint32_t nOff = (uint32_t)(np * 16 * UWSTR * 2) + kOff;
                uint32_t Bhi[4], Blo[4];
                ldsm_x4(Bhi, wHi + nOff);
                ldsm_x4(Blo, wLo + nOff);
                mma_f16(acc[np * 2],     A, Bhi[0], Bhi[1]);
                mma_f16(acc[np * 2],     A, Blo[0], Blo[1]);
                mma_f16(acc[np * 2 + 1], A, Bhi[2], Bhi[3]);
                mma_f16(acc[np * 2 + 1], A, Blo[2], Blo[3]);
            }
        }
    }

    // --- epilogue: bias + lrelu + direct STG.64 ---
    {
        const int rA = r0g + mchunk * 16 + (lane >> 2);
        const int rB = rA + 8;
        const int cb = nhalf * 112 + (lane & 3) * 2;
        #pragma unroll
        for (int n = 0; n < 14; n++) {
            int c = cb + n * 8;
            float b0 = bsm[c], b1 = bsm[c + 1];
            if (rA < N_NODES) {
                float2 v = make_float2(lrelu(acc[n][0] + b0), lrelu(acc[n][1] + b1));
                *(float2*)(out + (size_t)rA * HID + c) = v;
            }
            if (rB < N_NODES) {
                float2 v = make_float2(lrelu(acc[n][2] + b0), lrelu(acc[n][3] + b1));
                *(float2*)(out + (size_t)rB * HID + c) = v;
            }
        }
    }
}

// ---------------------------------------------------------------------------
extern "C" void kernel_launch(void* const* d_in, const int* in_sizes, int n_in,
                              void* d_out, int out_size)
{
    const float* h_n = (const float*)d_in[0];
    const float* h_e = (const float*)d_in[1];
    const int*   src = (const int*)d_in[2];
    const int*   dst = (const int*)d_in[3];
    const float* Wm  = (const float*)d_in[4];
    const float* bm  = (const float*)d_in[5];
    const float* Wh  = (const float*)d_in[6];
    const float* bh  = (const float*)d_in[7];
    float* out = (float*)d_out;

    cudaFuncSetAttribute(edge_kernel, cudaFuncAttributeMaxDynamicSharedMemorySize,
                         EDGE_SMEM_BYTES);
    cudaFuncSetAttribute(update_kernel, cudaFuncAttributeMaxDynamicSharedMemorySize,
                         UPD_SMEM_BYTES);

    zero_msum_kernel<<<2048, 256>>>();
    edge_kernel<<<152, 512, EDGE_SMEM_BYTES>>>(h_n, h_e, src, dst, Wm, bm);
    update_kernel<<<(N_NODES + 127) / 128, 512, UPD_SMEM_BYTES>>>(h_n, Wh, bh, out);
}

// round 16
// speedup vs baseline: 4.8176x; 1.0242x over previous
#include <cuda_runtime.h>
#include <cuda_fp16.h>
#include <cstdint>

#define N_NODES 50000
#define N_EDGES 500000
#define D_NODE  64
#define D_EDGE  32
#define MSG     160
#define HID     224
#define ALPHA   0.01f

#define NTILES  ((N_EDGES + 127) / 128)   // 3907

// 32 MB scratch for segment-sum accumulation.
// Zero-initialized at module load; update_kernel re-zeroes its slice each call,
// so every kernel_launch invocation sees zeros (graph-replay deterministic).
__device__ float g_msum[(size_t)N_NODES * MSG];

__device__ __forceinline__ float lrelu(float v) { return v > 0.f ? v : ALPHA * v; }

__device__ __forceinline__ uint32_t smem_u32(const void* p) {
    uint32_t a;
    asm("{ .reg .u64 t; cvta.to.shared.u64 t, %1; cvt.u32.u64 %0, t; }" : "=r"(a) : "l"(p));
    return a;
}

__device__ __forceinline__ void ldsm_x4(uint32_t* r, uint32_t addr) {
    asm volatile("ldmatrix.sync.aligned.m8n8.x4.shared.b16 {%0,%1,%2,%3}, [%4];"
                 : "=r"(r[0]), "=r"(r[1]), "=r"(r[2]), "=r"(r[3]) : "r"(addr));
}

__device__ __forceinline__ void mma_f16(float* d, const uint32_t* a,
                                        uint32_t b0, uint32_t b1) {
    asm volatile("mma.sync.aligned.m16n8k16.row.col.f32.f16.f16.f32 "
                 "{%0,%1,%2,%3}, {%4,%5,%6,%7}, {%8,%9}, {%0,%1,%2,%3};"
                 : "+f"(d[0]), "+f"(d[1]), "+f"(d[2]), "+f"(d[3])
                 : "r"(a[0]), "r"(a[1]), "r"(a[2]), "r"(a[3]), "r"(b0), "r"(b1));
}

// pack two floats into one f16x2 (lo = a, hi = b)
__device__ __forceinline__ uint32_t packh2(float a, float b) {
    uint32_t r;
    asm("cvt.rn.f16x2.f32 %0, %1, %2;" : "=r"(r) : "f"(b), "f"(a));
    return r;
}

// fp16 hi/lo split of a float4 (W prologue only)
__device__ __forceinline__ void splitW4(float4 v, uint2& hi, uint2& lo) {
    __half h0 = __float2half_rn(v.x), h1 = __float2half_rn(v.y);
    __half h2 = __float2half_rn(v.z), h3 = __float2half_rn(v.w);
    float l0 = v.x - __half2float(h0), l1 = v.y - __half2float(h1);
    float l2 = v.z - __half2float(h2), l3 = v.w - __half2float(h3);
    hi.x = ((uint32_t)__half_as_ushort(h1) << 16) | __half_as_ushort(h0);
    hi.y = ((uint32_t)__half_as_ushort(h3) << 16) | __half_as_ushort(h2);
    lo.x = packh2(l0, l1);
    lo.y = packh2(l2, l3);
}

// ---------------------------------------------------------------------------
// Kernel 1: persistent edge kernel (fp16 2-term), register-pipelined gather,
//   double-buffered X -> ONE barrier per tile.
//   Tile: 128 edges x 160 out, K=160. 512 threads.
//   16 warps = 8 m-chunks (16 edges) x 2 n-halves (80 outs)
// SMEM: X0 | X1 [128][168] f16 | WHI [160][168] f16 | WLO | bias | dsm0 | dsm1
// ---------------------------------------------------------------------------
#define XSTR  168
#define WSTR  168
#define SM_X0    0
#define SM_X1    43008
#define SM_WHI   86016
#define SM_WLO   139776
#define SM_BIAS  193536
#define SM_DSM0  194176
#define SM_DSM1  194688
#define EDGE_SMEM_BYTES 195200

__global__ __launch_bounds__(512, 1) void edge_kernel(
    const float* __restrict__ h_n, const float* __restrict__ h_e,
    const int* __restrict__ src, const int* __restrict__ dst,
    const float* __restrict__ Wm, const float* __restrict__ bm)
{
    extern __shared__ char smem[];
    const uint32_t sbase = smem_u32(smem);
    const int tid  = threadIdx.x;
    const int wid  = tid >> 5;
    const int lane = tid & 31;

    float* bsm = (float*)(smem + SM_BIAS);

    // --- prologue: convert W_msg to fp16 hi/lo into smem ---
    for (int i = tid; i < MSG * 40; i += 512) {
        int r = i / 40, c4 = (i % 40) * 4;
        float4 v = __ldg((const float4*)(Wm + r * MSG + c4));
        uint2 hi, lo; splitW4(v, hi, lo);
        uint32_t off = (uint32_t)(r * WSTR + c4) * 2u;
        *(uint2*)(smem + SM_WHI + off) = hi;
        *(uint2*)(smem + SM_WLO + off) = lo;
    }
    if (tid < MSG) bsm[tid] = __ldg(bm + tid);

    const int q  = lane >> 3;
    const int ri = lane & 7;
    const int mchunk = wid & 7;       // 16-edge row group
    const int nhalf  = wid >> 3;      // 80-output column half
    const uint32_t aLane = (uint32_t)(((mchunk * 16 + (q & 1) * 8 + ri) * XSTR +
                                       (q >> 1) * 8) * 2);
    const uint32_t bLane = (uint32_t)(((nhalf * 80 + (q >> 1) * 8 + ri) * WSTR +
                                       (q & 1) * 8) * 2);
    const uint32_t aX0 = sbase + SM_X0 + aLane;
    const uint32_t aX1 = sbase + SM_X1 + aLane;
    const uint32_t wHi = sbase + SM_WHI + bLane;
    const uint32_t wLo = sbase + SM_WLO + bLane;

    // gather mapping: 4 threads per edge, 10 float4 each
    const int gle = tid >> 2;          // edge slot 0..127
    const int gj0 = (tid & 3) * 10;    // first float4 index

    // held gather state for the NEXT tile to be stored
    float4 G[10];
    int    Gd = -1;

    auto do_gather = [&](int tt) {
        const int e = tt * 128 + gle;
        const bool valid = (tt < NTILES) && (e < N_EDGES);
        int s = 0, d = 0;
        if (valid) { s = __ldg(src + e); d = __ldg(dst + e); }
        Gd = valid ? d : -1;
        const float4* ps = (const float4*)(h_n + (size_t)s * D_NODE);
        const float4* pd = (const float4*)(h_n + (size_t)d * D_NODE);
        const float4* pe = (const float4*)(h_e + (size_t)e * D_EDGE);
        #pragma unroll
        for (int i = 0; i < 10; i++) {
            const int j = gj0 + i;
            float4 v = make_float4(0.f, 0.f, 0.f, 0.f);
            if (valid) {
                if (j < 16)      v = __ldg(ps + j);
                else if (j < 32) v = __ldg(pd + (j - 16));
                else             v = __ldg(pe + (j - 32));
            }
            G[i] = v;
        }
    };

    auto do_store = [&](int buf) {
        char* xb = smem + (buf ? SM_X1 : SM_X0);
        int*  dd = (int*)(smem + (buf ? SM_DSM1 : SM_DSM0));
        if ((tid & 3) == 0) dd[gle] = Gd;
        #pragma unroll
        for (int i = 0; i < 10; i++) {
            const int j = gj0 + i;
            uint2 hv;
            hv.x = packh2(G[i].x, G[i].y);
            hv.y = packh2(G[i].z, G[i].w);
            *(uint2*)(xb + (uint32_t)(gle * XSTR + j * 4) * 2u) = hv;
        }
    };

    // pipeline prologue: gather+store tile0 into buf0, then gather tile1
    do_gather(blockIdx.x);
    do_store(0);
    __syncthreads();             // W, bias, X0, dsm0 ready
    do_gather(blockIdx.x + gridDim.x);

    int b = 0;
    for (int tile = blockIdx.x; tile < NTILES; tile += gridDim.x) {
        const uint32_t aX = b ? aX1 : aX0;
        const int* dsm = (const int*)(smem + (b ? SM_DSM1 : SM_DSM0));

        // --- compute: warp covers 16 edges x 80 outs: acc[10 n8][4] ---
        float acc[10][4];
        #pragma unroll
        for (int n = 0; n < 10; n++)
            #pragma unroll
            for (int i = 0; i < 4; i++) acc[n][i] = 0.f;

        #pragma unroll 1
        for (int kk = 0; kk < 10; kk++) {
            const uint32_t kOff = (uint32_t)(kk * 32);
            uint32_t A[4];
            ldsm_x4(A, aX + kOff);
            #pragma unroll
            for (int np = 0; np < 5; np++) {
                const uint32_t nOff = (uint32_t)(np * 16 * WSTR * 2) + kOff;
                uint32_t Bhi[4], Blo[4];
                ldsm_x4(Bhi, wHi + nOff);
                ldsm_x4(Blo, wLo + nOff);
                mma_f16(acc[np * 2],     A, Bhi[0], Bhi[1]);
                mma_f16(acc[np * 2],     A, Blo[0], Blo[1]);
                mma_f16(acc[np * 2 + 1], A, Bhi[2], Bhi[3]);
                mma_f16(acc[np * 2 + 1], A, Blo[2], Blo[3]);
            }
        }

        // --- epilogue: shfl pairs into v4, bias + lrelu + red.v4 scatter ---
        {
            const int g  = lane & 3;
            const int r0 = mchunk * 16 + (lane >> 2);
            const int d0 = dsm[r0];
            const int d1 = dsm[r0 + 8];
            const int cb = nhalf * 80;
            #pragma unroll
            for (int t = 0; t < 5; t++) {
                const int n0 = 2 * t, n1 = 2 * t + 1;
                #pragma unroll
                for (int h = 0; h < 2; h++) {
                    float ox0 = acc[n0][2 * h], ox1 = acc[n0][2 * h + 1];
                    float oy0 = acc[n1][2 * h], oy1 = acc[n1][2 * h + 1];
                    float s0 = (g & 1) ? ox0 : oy0;
                    float s1 = (g & 1) ? ox1 : oy1;
                    float rc0 = __shfl_xor_sync(0xffffffffu, s0, 1);
                    float rc1 = __shfl_xor_sync(0xffffffffu, s1, 1);
                    float v0, v1, v2, v3;
                    if (g & 1) { v0 = rc0; v1 = rc1; v2 = oy0; v3 = oy1; }
                    else       { v0 = ox0; v1 = ox1; v2 = rc0; v3 = rc1; }
                    const int c = cb + ((g & 1) ? n1 : n0) * 8 + (g & 2) * 2;
                    const int d = h ? d1 : d0;
                    if (d >= 0) {
                        float4 bb = *(const float4*)(bsm + c);
                        v0 = lrelu(v0 + bb.x); v1 = lrelu(v1 + bb.y);
                        v2 = lrelu(v2 + bb.z); v3 = lrelu(v3 + bb.w);
                        asm volatile("red.global.add.v4.f32 [%0], {%1, %2, %3, %4};"
                                     :: "l"(g_msum + (size_t)d * MSG + c),
                                        "f"(v0), "f"(v1), "f"(v2), "f"(v3) : "memory");
                    }
                }
            }
        }

        // --- store next tile (held in G) into the other buffer ---
        do_store(b ^ 1);
        __syncthreads();          // single barrier per tile
        do_gather(tile + 2 * gridDim.x);
        b ^= 1;
    }
}

// ---------------------------------------------------------------------------
// Kernel 2: update GEMM (fp16 2-term), 512 threads; also re-zeroes its
//   g_msum slice after the last read (keeps calls deterministic, removes
//   the separate zero kernel).
// ---------------------------------------------------------------------------
#define UXSTR 120
#define UWSTR 120
#define USM_X    0
#define USM_WHI  30720
#define USM_WLO  84480
#define USM_BIAS 138240
#define UPD_SMEM_BYTES 139136

__global__ __launch_bounds__(512, 1) void update_kernel(
    const float* __restrict__ h_n, const float* __restrict__ Wh,
    const float* __restrict__ bh, float* __restrict__ out)
{
    extern __shared__ char smem[];
    const uint32_t sbase = smem_u32(smem);
    const int tid  = threadIdx.x;
    const int wid  = tid >> 5;
    const int lane = tid & 31;
    const int r0g  = blockIdx.x * 128;

    float* bsm = (float*)(smem + USM_BIAS);
    if (tid < HID) bsm[tid] = __ldg(bh + tid);

    const int q  = lane >> 3;
    const int ri = lane & 7;
    const int mchunk = wid & 7;
    const int nhalf  = wid >> 3;

    const uint32_t aLane = (uint32_t)(((mchunk * 16 + (q & 1) * 8 + ri) * UXSTR +
                                       (q >> 1) * 8) * 2);
    const uint32_t bLane = (uint32_t)(((nhalf * 112 + (q >> 1) * 8 + ri) * UWSTR +
                                       (q & 1) * 8) * 2);
    const uint32_t aX  = sbase + USM_X + aLane;
    const uint32_t wHi = sbase + USM_WHI + bLane;
    const uint32_t wLo = sbase + USM_WLO + bLane;

    float acc[14][4];
    #pragma unroll
    for (int n = 0; n < 14; n++)
        #pragma unroll
        for (int i = 0; i < 4; i++) acc[n][i] = 0.f;

    for (int kc = 0; kc < 2; kc++) {
        const int kbase = kc * 112;
        __syncthreads();   // previous chunk mma done (and bsm written on kc=0)

        for (int i = tid; i < HID * 28; i += 512) {
            int r = i / 28, c4 = (i % 28) * 4;
            float4 v = __ldg((const float4*)(Wh + (size_t)r * HID + kbase + c4));
            uint2 hi, lo; splitW4(v, hi, lo);
            uint32_t off = (uint32_t)(r * UWSTR + c4) * 2u;
            *(uint2*)(smem + USM_WHI + off) = hi;
            *(uint2*)(smem + USM_WLO + off) = lo;
        }
        for (int i = tid; i < 128 * 28; i += 512) {
            int lr = i / 28, c4 = (i % 28) * 4;
            int row = r0g + lr;
            int kg = kbase + c4;
            float4 v = make_float4(0.f, 0.f, 0.f, 0.f);
            if (row < N_NODES) {
                if (kg < MSG) v = *(const float4*)(g_msum + (size_t)row * MSG + kg);
                else          v = *(const float4*)(h_n + (size_t)row * D_NODE + (kg - MSG));
            }
            uint2 hv;
            hv.x = packh2(v.x, v.y);
            hv.y = packh2(v.z, v.w);
            *(uint2*)(smem + USM_X + (uint32_t)(lr * UXSTR + c4) * 2u) = hv;
        }
        __syncthreads();

        // After the LAST read of this block's g_msum slice: re-zero it for the
        // next kernel_launch call. STGs drain under the MMA below.
        if (kc == 1) {
            for (int i = tid; i < 128 * 40; i += 512) {
                int lr = i / 40, c4 = (i % 40) * 4;
                int row = r0g + lr;
                if (row < N_NODES)
                    *(float4*)(g_msum + (size_t)row * MSG + c4) =
                        make_float4(0.f, 0.f, 0.f, 0.f);
            }
        }

        #pragma unroll 1
        for (int kk = 0; kk < 7; kk++) {
            const uint32_t kOff = (uint32_t)(kk * 32);
            uint32_t A[4];
            ldsm_x4(A, aX + kOff);
            #pragma unroll
            for (int np = 0; np < 7; np++) {
                const uint32_t nOff = (uint32_t)(np * 16 * UWSTR * 2) + kOff;
                uint32_t Bhi[4], Blo[4];
                ldsm_x4(Bhi, wHi + nOff);
                ldsm_x4(Blo, wLo + nOff);
                mma_f16(acc[np * 2],     A, Bhi[0], Bhi[1]);
                mma_f16(acc[np * 2],     A, Blo[0], Blo[1]);
                mma_f16(acc[np * 2 + 1], A, Bhi[2], Bhi[3]);
                mma_f16(acc[np * 2 + 1], A, Blo[2], Blo[3]);
            }
        }
    }

    // --- epilogue: bias + lrelu + direct STG.64 ---
    {
        const int rA = r0g + mchunk * 16 + (lane >> 2);
        const int rB = rA + 8;
        const int cb = nhalf * 112 + (lane & 3) * 2;
        #pragma unroll
        for (int n = 0; n < 14; n++) {
            int c = cb + n * 8;
            float b0 = bsm[c], b1 = bsm[c + 1];
            if (rA < N_NODES) {
                float2 v = make_float2(lrelu(acc[n][0] + b0), lrelu(acc[n][1] + b1));
                *(float2*)(out + (size_t)rA * HID + c) = v;
            }
            if (rB < N_NODES) {
                float2 v = make_float2(lrelu(acc[n][2] + b0), lrelu(acc[n][3] + b1));
                *(float2*)(out + (size_t)rB * HID + c) = v;
            }
        }
    }
}

// ---------------------------------------------------------------------------
extern "C" void kernel_launch(void* const* d_in, const int* in_sizes, int n_in,
                              void* d_out, int out_size)
{
    const float* h_n = (const float*)d_in[0];
    const float* h_e = (const float*)d_in[1];
    const int*   src = (const int*)d_in[2];
    const int*   dst = (const int*)d_in[3];
    const float* Wm  = (const float*)d_in[4];
    const float* bm  = (const float*)d_in[5];
    const float* Wh  = (const float*)d_in[6];
    const float* bh  = (const float*)d_in[7];
    float* out = (float*)d_out;

    cudaFuncSetAttribute(edge_kernel, cudaFuncAttributeMaxDynamicSharedMemorySize,
                         EDGE_SMEM_BYTES);
    cudaFuncSetAttribute(update_kernel, cudaFuncAttributeMaxDynamicSharedMemorySize,
                         UPD_SMEM_BYTES);

    edge_kernel<<<152, 512, EDGE_SMEM_BYTES>>>(h_n, h_e, src, dst, Wm, bm);
    update_kernel<<<(N_NODES + 127) / 128, 512, UPD_SMEM_BYTES>>>(h_n, Wh, bh, out);
}